// round 7
// baseline (speedup 1.0000x reference)
#include <cuda_runtime.h>
#include <cuda_bf16.h>
#include <stdint.h>
#include <math.h>

// ---------- problem constants ----------
#define NROWS    131072           // 512 graphs * 256 nodes
#define INDIM    128
#define HIDN     128
#define D2       256
#define MTILE    64               // rows per CTA
#define NCTA     (NROWS / MTILE)  // 2048
#define NTHREADS 512              // 16 warps: wm in {0..3} (16-row), wn in {0..3} (64-col)

// ---------- smem layout (bytes) ----------
#define SM_AHI   0
#define SM_ALO   32768
#define SM_EMB   65536
#define SM_B1    66048
#define SM_B2    67072
#define SM_W3    68096
#define SM_RED   70144
#define SM_TOTAL 72192

// B fragments, fragment-major in global scratch:
// u32 index = ((((l*2+p)*16 + ks)*32 + lane)*64) + NT*2 + reg
__device__ uint32_t g_Bf[131072];   // 512KB

static __device__ __forceinline__ uint32_t pack_bf(__nv_bfloat16 a, __nv_bfloat16 b) {
    return ((uint32_t)__bfloat16_as_ushort(b) << 16) | (uint32_t)__bfloat16_as_ushort(a);
}
static __device__ __forceinline__ void split_bf(float v, __nv_bfloat16& hi, __nv_bfloat16& lo) {
    hi = __float2bfloat16(v);
    lo = __float2bfloat16(v - __bfloat162float(hi));
}
static __device__ __forceinline__ uint32_t s2u(const void* p) {
    uint32_t a;
    asm("{ .reg .u64 t; cvta.to.shared.u64 t, %1; cvt.u32.u64 %0, t; }"
        : "=r"(a) : "l"(p));
    return a;
}

// ---------- prep: split W1/W2 into bf16 hi/lo fragments ----------
__global__ void prep_weights(const float* __restrict__ W1, const float* __restrict__ W2) {
    int i = blockIdx.x * blockDim.x + threadIdx.x;
    int reg  = i & 1;
    int NT   = (i >> 1) & 31;
    int lane = (i >> 6) & 31;
    int ks   = (i >> 11) & 15;
    int p    = (i >> 15) & 1;
    int l    = i >> 16;
    const float* W = l ? W2 : W1;
    int k0 = ks * 16 + (lane & 3) * 2 + reg * 8;
    int n  = NT * 8 + (lane >> 2);
    float v0 = W[k0 * 256 + n];
    float v1 = W[(k0 + 1) * 256 + n];
    __nv_bfloat16 h0, l0, h1, l1;
    split_bf(v0, h0, l0);
    split_bf(v1, h1, l1);
    g_Bf[i] = (p == 0) ? pack_bf(h0, h1) : pack_bf(l0, l1);
}

// ---------- mma / ldmatrix wrappers ----------
static __device__ __forceinline__ void mma_bf16(float* d, const uint32_t* a,
                                                uint32_t b0, uint32_t b1) {
    asm volatile(
        "mma.sync.aligned.m16n8k16.row.col.f32.bf16.bf16.f32 "
        "{%0,%1,%2,%3}, {%4,%5,%6,%7}, {%8,%9}, {%0,%1,%2,%3};"
        : "+f"(d[0]), "+f"(d[1]), "+f"(d[2]), "+f"(d[3])
        : "r"(a[0]), "r"(a[1]), "r"(a[2]), "r"(a[3]), "r"(b0), "r"(b1));
}
static __device__ __forceinline__ void ldsm4(uint32_t* r, uint32_t saddr) {
    asm volatile("ldmatrix.sync.aligned.m8n8.x4.shared.b16 {%0,%1,%2,%3}, [%4];"
                 : "=r"(r[0]), "=r"(r[1]), "=r"(r[2]), "=r"(r[3]) : "r"(saddr));
}

// A smem byte offset for (row r, k); k-halves (16B) swapped when r&4.
static __device__ __forceinline__ uint32_t offA(int r, int k) {
    uint32_t c = (uint32_t)(k & 15);
    uint32_t cp = (c + (uint32_t)((r & 4) << 1)) & 15u;
    return ((uint32_t)(k >> 4) << 11) + ((uint32_t)r << 5) + (cp << 1);
}

// ---------- one GEMM layer: acc += A(smem) x B(frag-major global) ----------
static __device__ __forceinline__ void gemm_layer(uint32_t smbA,
                                                  const uint32_t* __restrict__ gB,
                                                  uint32_t aoff,   // per-lane ldmatrix offset
                                                  int lane, int wn,
                                                  float (&acc)[8][4]) {
    const uint32_t lwoff = (uint32_t)lane * 64 + (uint32_t)wn * 16;

    #pragma unroll
    for (int nt = 0; nt < 8; nt++)
        #pragma unroll
        for (int c = 0; c < 4; c++)
            acc[nt][c] = 0.f;

    #pragma unroll
    for (int ks = 0; ks < 16; ks++) {
        // B fragments (L2 / L1 resident)
        union { uint4 q[4]; uint32_t b[16]; } BH, BL;
        const uint4* p  = (const uint4*)(gB + (uint32_t)ks * 2048 + lwoff);
        const uint4* pl = (const uint4*)(gB + 32768 + (uint32_t)ks * 2048 + lwoff);
        #pragma unroll
        for (int i = 0; i < 4; i++) { BH.q[i] = p[i]; BL.q[i] = pl[i]; }

        // A fragments via ldmatrix
        uint32_t aH[4], aL[4];
        uint32_t abase = smbA + ((uint32_t)ks << 11) + aoff;
        ldsm4(aH, abase);
        ldsm4(aL, abase + 32768);

        #pragma unroll
        for (int nt = 0; nt < 8; nt++)
            mma_bf16(acc[nt], aH, BH.b[nt * 2], BH.b[nt * 2 + 1]);
        #pragma unroll
        for (int nt = 0; nt < 8; nt++)
            mma_bf16(acc[nt], aH, BL.b[nt * 2], BL.b[nt * 2 + 1]);
        #pragma unroll
        for (int nt = 0; nt < 8; nt++)
            mma_bf16(acc[nt], aL, BH.b[nt * 2], BH.b[nt * 2 + 1]);
    }
}

// ---------- main fused kernel ----------
__global__ __launch_bounds__(NTHREADS, 1)
void fused_hmma_kernel(const float* __restrict__ last,
                       const float* __restrict__ h,
                       const float* __restrict__ We,
                       const float* __restrict__ be,
                       const float* __restrict__ b1,
                       const float* __restrict__ b2,
                       const float* __restrict__ W3,
                       const float* __restrict__ b3,
                       float* __restrict__ out) {
    extern __shared__ char sm[];
    const uint32_t smb = s2u(sm);
    const int tid  = threadIdx.x;
    const int lane = tid & 31;
    const int wid  = tid >> 5;
    const int wm   = wid >> 2;       // 0..3 (16-row block)
    const int wn   = wid & 3;        // 0..3 (64-col slice)
    const int r0   = blockIdx.x * MTILE;
    const int grp  = r0 >> 8;

    float* sEmb = (float*)(sm + SM_EMB);
    float* sB1  = (float*)(sm + SM_B1);
    float* sB2  = (float*)(sm + SM_B2);
    float* sW3  = (float*)(sm + SM_W3);
    float* sRed = (float*)(sm + SM_RED);

    if (tid < 256) {
        sB1[tid] = b1[tid];
        sB2[tid] = b2[tid];
        sW3[tid]       = W3[tid];
        sW3[tid + 256] = W3[tid + 256];
    }

    if (tid < HIDN) {
        float acc = be[tid];
        const float* lrow = last + (size_t)grp * INDIM;
        #pragma unroll 4
        for (int k = 0; k < INDIM; k++)
            acc = fmaf(lrow[k], We[k * HIDN + tid], acc);
        sEmb[tid] = acc;
    }

    // A tile, h half: 64 rows x 128 k
    for (int idx = tid; idx < MTILE * 32; idx += NTHREADS) {
        int r = idx >> 5, kq = idx & 31, k = kq * 4;
        float4 v = *(const float4*)(h + (size_t)(r0 + r) * HIDN + k);
        __nv_bfloat16 h0, l0, h1, l1, h2, l2, h3, l3;
        split_bf(v.x, h0, l0); split_bf(v.y, h1, l1);
        split_bf(v.z, h2, l2); split_bf(v.w, h3, l3);
        uint32_t off = offA(r, k);
        *(uint2*)(sm + SM_AHI + off) = make_uint2(pack_bf(h0, h1), pack_bf(h2, h3));
        *(uint2*)(sm + SM_ALO + off) = make_uint2(pack_bf(l0, l1), pack_bf(l2, l3));
    }
    __syncthreads();

    // A tile, embed half: k 128..255, broadcast across rows
    for (int idx = tid; idx < MTILE * 32; idx += NTHREADS) {
        int r = idx >> 5, kq = idx & 31, k = 128 + kq * 4;
        float4 v = *(const float4*)(sEmb + kq * 4);
        __nv_bfloat16 h0, l0, h1, l1, h2, l2, h3, l3;
        split_bf(v.x, h0, l0); split_bf(v.y, h1, l1);
        split_bf(v.z, h2, l2); split_bf(v.w, h3, l3);
        uint32_t off = offA(r, k);
        *(uint2*)(sm + SM_AHI + off) = make_uint2(pack_bf(h0, h1), pack_bf(h2, h3));
        *(uint2*)(sm + SM_ALO + off) = make_uint2(pack_bf(l0, l1), pack_bf(l2, l3));
    }
    __syncthreads();

    const int g   = lane >> 2;
    const int tig = lane & 3;

    // per-lane ldmatrix address offset (within a k-step block)
    // q = lane>>3: 0 -> rows 0-7 klo, 1 -> rows 8-15 klo, 2 -> rows 0-7 khi, 3 -> rows 8-15 khi
    uint32_t aoff;
    {
        int q = lane >> 3, rr = lane & 7;
        int row = wm * 16 + (q & 1) * 8 + rr;
        int khalf = q >> 1;
        aoff = (uint32_t)(row * 32 + (((khalf ^ ((row >> 2) & 1)) & 1) << 4));
    }

    float acc[8][4];

    // ===== Layer 1 =====
    gemm_layer(smb + SM_AHI, g_Bf, aoff, lane, wn, acc);
    __syncthreads();

    // epilogue 1: tanh(+b1) -> re-split into A smem
    {
        int rA = wm * 16 + g;
        int rB = rA + 8;
        #pragma unroll
        for (int nt = 0; nt < 8; nt++) {
            int c0 = wn * 64 + nt * 8 + tig * 2;
            float t0 = tanhf(acc[nt][0] + sB1[c0]);
            float t1 = tanhf(acc[nt][1] + sB1[c0 + 1]);
            float t2 = tanhf(acc[nt][2] + sB1[c0]);
            float t3 = tanhf(acc[nt][3] + sB1[c0 + 1]);
            __nv_bfloat16 h0, l0, h1, l1;
            split_bf(t0, h0, l0); split_bf(t1, h1, l1);
            uint32_t oA = offA(rA, c0);
            *(uint32_t*)(sm + SM_AHI + oA) = pack_bf(h0, h1);
            *(uint32_t*)(sm + SM_ALO + oA) = pack_bf(l0, l1);
            split_bf(t2, h0, l0); split_bf(t3, h1, l1);
            uint32_t oB = offA(rB, c0);
            *(uint32_t*)(sm + SM_AHI + oB) = pack_bf(h0, h1);
            *(uint32_t*)(sm + SM_ALO + oB) = pack_bf(l0, l1);
        }
    }
    __syncthreads();

    // ===== Layer 2 =====
    gemm_layer(smb + SM_AHI, g_Bf + 65536, aoff, lane, wn, acc);

    // epilogue 2: tanh(+b2), dot with W3, reduce
    float e[2][2];   // [rowhalf][comp]
    e[0][0] = e[0][1] = e[1][0] = e[1][1] = 0.f;

    #pragma unroll
    for (int nt = 0; nt < 8; nt++) {
        int c0 = wn * 64 + nt * 8 + tig * 2;
        float o0 = tanhf(acc[nt][0] + sB2[c0]);
        float o1 = tanhf(acc[nt][1] + sB2[c0 + 1]);
        float o2 = tanhf(acc[nt][2] + sB2[c0]);
        float o3 = tanhf(acc[nt][3] + sB2[c0 + 1]);
        float w00 = sW3[2 * c0],     w01 = sW3[2 * c0 + 1];
        float w10 = sW3[2 * c0 + 2], w11 = sW3[2 * c0 + 3];
        e[0][0] = fmaf(o0, w00, fmaf(o1, w10, e[0][0]));
        e[0][1] = fmaf(o0, w01, fmaf(o1, w11, e[0][1]));
        e[1][0] = fmaf(o2, w00, fmaf(o3, w10, e[1][0]));
        e[1][1] = fmaf(o2, w01, fmaf(o3, w11, e[1][1]));
    }
    #pragma unroll
    for (int off = 1; off <= 2; off <<= 1)
        #pragma unroll
        for (int hh = 0; hh < 2; hh++) {
            e[hh][0] += __shfl_xor_sync(0xffffffffu, e[hh][0], off);
            e[hh][1] += __shfl_xor_sync(0xffffffffu, e[hh][1], off);
        }
    if (tig == 0) {
        #pragma unroll
        for (int hh = 0; hh < 2; hh++) {
            int row = wm * 16 + g + hh * 8;
            sRed[wn * 128 + row * 2 + 0] = e[hh][0];
            sRed[wn * 128 + row * 2 + 1] = e[hh][1];
        }
    }
    __syncthreads();

    if (tid < 128) {
        int row  = tid >> 1;
        int comp = tid & 1;
        float s = sRed[row * 2 + comp] + sRed[128 + row * 2 + comp]
                + sRed[256 + row * 2 + comp] + sRed[384 + row * 2 + comp]
                + b3[comp];
        int rg = r0 + row;
        out[(size_t)(rg >> 8) * 512 + (size_t)(rg & 255) * 2 + comp] = s;
    }
}

extern "C" void kernel_launch(void* const* d_in, const int* in_sizes, int n_in,
                              void* d_out, int out_size) {
    const float* last = (const float*)d_in[0];
    const float* h    = (const float*)d_in[1];
    const float* We   = (const float*)d_in[2];
    const float* be   = (const float*)d_in[3];
    const float* W1   = (const float*)d_in[4];
    const float* b1   = (const float*)d_in[5];
    const float* W2   = (const float*)d_in[6];
    const float* b2   = (const float*)d_in[7];
    const float* W3   = (const float*)d_in[8];
    const float* b3   = (const float*)d_in[9];
    float* out = (float*)d_out;

    prep_weights<<<512, 256>>>(W1, W2);

    cudaFuncSetAttribute(fused_hmma_kernel,
                         cudaFuncAttributeMaxDynamicSharedMemorySize, SM_TOTAL);
    fused_hmma_kernel<<<NCTA, NTHREADS, SM_TOTAL>>>(last, h, We, be, b1, b2, W3, b3, out);
}

// round 11
// speedup vs baseline: 2.0653x; 2.0653x over previous
#include <cuda_runtime.h>
#include <cuda_bf16.h>
#include <stdint.h>
#include <math.h>

// ---------- problem constants ----------
#define NROWS    131072           // 512 graphs * 256 nodes
#define INDIM    128
#define HIDN     128
#define D2       256
#define MTILE    64               // rows per CTA
#define NCTA     (NROWS / MTILE)  // 2048
#define NTHREADS 512              // 16 warps: wm in {0..3} (16-row), wn in {0..3} (64-col)

// ---------- smem layout (bytes) ----------
#define SM_AHI   0
#define SM_ALO   32768
#define SM_EMB   65536
#define SM_B1    66048
#define SM_B2    67072
#define SM_W3    68096
#define SM_RED   70144
#define SM_TOTAL 72192

// B fragments in global scratch, COALESCED layout:
// u32 idx = ((((l*2+p)*16 + ks)*4 + wn)*4 + q)*128 + lane*4 + j
// -> for fixed (l,p,ks,wn,q) the warp's 512B are contiguous.
__device__ uint32_t g_Bf[131072];   // 512KB

static __device__ __forceinline__ uint32_t pack_bf(__nv_bfloat16 a, __nv_bfloat16 b) {
    return ((uint32_t)__bfloat16_as_ushort(b) << 16) | (uint32_t)__bfloat16_as_ushort(a);
}
static __device__ __forceinline__ void split_bf(float v, __nv_bfloat16& hi, __nv_bfloat16& lo) {
    hi = __float2bfloat16(v);
    lo = __float2bfloat16(v - __bfloat162float(hi));
}
static __device__ __forceinline__ uint32_t s2u(const void* p) {
    uint32_t a;
    asm("{ .reg .u64 t; cvta.to.shared.u64 t, %1; cvt.u32.u64 %0, t; }"
        : "=r"(a) : "l"(p));
    return a;
}

// ---------- prep: split W1/W2 into bf16 hi/lo fragments (coalesced layout) ----------
__global__ void prep_weights(const float* __restrict__ W1, const float* __restrict__ W2) {
    int i = blockIdx.x * blockDim.x + threadIdx.x;   // 0..131071
    int j    = i & 3;
    int lane = (i >> 2) & 31;
    int q    = (i >> 7) & 3;
    int wn   = (i >> 9) & 3;
    int ks   = (i >> 11) & 15;
    int p    = (i >> 15) & 1;
    int l    = i >> 16;
    int s   = q * 4 + j;          // u32 slot within the warp's 16-u32 fragment set
    int nt  = s >> 1;
    int reg = s & 1;
    int NT  = wn * 8 + nt;
    const float* W = l ? W2 : W1;
    int k0 = ks * 16 + (lane & 3) * 2 + reg * 8;
    int n  = NT * 8 + (lane >> 2);
    float v0 = W[k0 * 256 + n];
    float v1 = W[(k0 + 1) * 256 + n];
    __nv_bfloat16 h0, l0, h1, l1;
    split_bf(v0, h0, l0);
    split_bf(v1, h1, l1);
    g_Bf[i] = (p == 0) ? pack_bf(h0, h1) : pack_bf(l0, l1);
}

// ---------- mma / ldmatrix wrappers ----------
static __device__ __forceinline__ void mma_bf16(float* d, const uint32_t* a,
                                                uint32_t b0, uint32_t b1) {
    asm volatile(
        "mma.sync.aligned.m16n8k16.row.col.f32.bf16.bf16.f32 "
        "{%0,%1,%2,%3}, {%4,%5,%6,%7}, {%8,%9}, {%0,%1,%2,%3};"
        : "+f"(d[0]), "+f"(d[1]), "+f"(d[2]), "+f"(d[3])
        : "r"(a[0]), "r"(a[1]), "r"(a[2]), "r"(a[3]), "r"(b0), "r"(b1));
}
static __device__ __forceinline__ void ldsm4(uint32_t* r, uint32_t saddr) {
    asm volatile("ldmatrix.sync.aligned.m8n8.x4.shared.b16 {%0,%1,%2,%3}, [%4];"
                 : "=r"(r[0]), "=r"(r[1]), "=r"(r[2]), "=r"(r[3]) : "r"(saddr));
}

// A smem byte offset for (row r, k); k-halves (16B) swapped when r&4.
static __device__ __forceinline__ uint32_t offA(int r, int k) {
    uint32_t c = (uint32_t)(k & 15);
    uint32_t cp = (c + (uint32_t)((r & 4) << 1)) & 15u;
    return ((uint32_t)(k >> 4) << 11) + ((uint32_t)r << 5) + (cp << 1);
}

// ---------- one GEMM layer: acc += A(smem) x B(frag-major global, coalesced) ----------
static __device__ __forceinline__ void gemm_layer(uint32_t smbA,
                                                  const uint32_t* __restrict__ gB,
                                                  uint32_t aoff,
                                                  int lane, int wn,
                                                  float (&acc)[8][4]) {
    // per-(ks) base: ks*2048 + wn*512 + lane*4 u32; q stride = 128 u32 = 32 uint4
    const uint32_t lwoff = (uint32_t)wn * 512 + (uint32_t)lane * 4;

    #pragma unroll
    for (int nt = 0; nt < 8; nt++)
        #pragma unroll
        for (int c = 0; c < 4; c++)
            acc[nt][c] = 0.f;

    #pragma unroll
    for (int ks = 0; ks < 16; ks++) {
        union { uint4 q[4]; uint32_t b[16]; } BH, BL;
        const uint4* pH = (const uint4*)(gB + (uint32_t)ks * 2048 + lwoff);
        const uint4* pL = (const uint4*)(gB + 32768 + (uint32_t)ks * 2048 + lwoff);
        #pragma unroll
        for (int i = 0; i < 4; i++) {
            BH.q[i] = pH[i * 32];      // +q*128 u32, fully coalesced 512B blocks
            BL.q[i] = pL[i * 32];
        }

        uint32_t aH[4], aL[4];
        uint32_t abase = smbA + ((uint32_t)ks << 11) + aoff;
        ldsm4(aH, abase);
        ldsm4(aL, abase + 32768);

        #pragma unroll
        for (int nt = 0; nt < 8; nt++)
            mma_bf16(acc[nt], aH, BH.b[nt * 2], BH.b[nt * 2 + 1]);
        #pragma unroll
        for (int nt = 0; nt < 8; nt++)
            mma_bf16(acc[nt], aH, BL.b[nt * 2], BL.b[nt * 2 + 1]);
        #pragma unroll
        for (int nt = 0; nt < 8; nt++)
            mma_bf16(acc[nt], aL, BH.b[nt * 2], BH.b[nt * 2 + 1]);
    }
}

// ---------- main fused kernel ----------
__global__ __launch_bounds__(NTHREADS, 1)
void fused_hmma_kernel(const float* __restrict__ last,
                       const float* __restrict__ h,
                       const float* __restrict__ We,
                       const float* __restrict__ be,
                       const float* __restrict__ b1,
                       const float* __restrict__ b2,
                       const float* __restrict__ W3,
                       const float* __restrict__ b3,
                       float* __restrict__ out) {
    extern __shared__ char sm[];
    const uint32_t smb = s2u(sm);
    const int tid  = threadIdx.x;
    const int lane = tid & 31;
    const int wid  = tid >> 5;
    const int wm   = wid >> 2;
    const int wn   = wid & 3;
    const int r0   = blockIdx.x * MTILE;
    const int grp  = r0 >> 8;

    float* sEmb = (float*)(sm + SM_EMB);
    float* sB1  = (float*)(sm + SM_B1);
    float* sB2  = (float*)(sm + SM_B2);
    float* sW3  = (float*)(sm + SM_W3);
    float* sRed = (float*)(sm + SM_RED);

    if (tid < 256) {
        sB1[tid] = b1[tid];
        sB2[tid] = b2[tid];
        sW3[tid]       = W3[tid];
        sW3[tid + 256] = W3[tid + 256];
    }

    if (tid < HIDN) {
        float acc = be[tid];
        const float* lrow = last + (size_t)grp * INDIM;
        #pragma unroll 4
        for (int k = 0; k < INDIM; k++)
            acc = fmaf(lrow[k], We[k * HIDN + tid], acc);
        sEmb[tid] = acc;
    }

    // A tile, h half: 64 rows x 128 k
    for (int idx = tid; idx < MTILE * 32; idx += NTHREADS) {
        int r = idx >> 5, kq = idx & 31, k = kq * 4;
        float4 v = *(const float4*)(h + (size_t)(r0 + r) * HIDN + k);
        __nv_bfloat16 h0, l0, h1, l1, h2, l2, h3, l3;
        split_bf(v.x, h0, l0); split_bf(v.y, h1, l1);
        split_bf(v.z, h2, l2); split_bf(v.w, h3, l3);
        uint32_t off = offA(r, k);
        *(uint2*)(sm + SM_AHI + off) = make_uint2(pack_bf(h0, h1), pack_bf(h2, h3));
        *(uint2*)(sm + SM_ALO + off) = make_uint2(pack_bf(l0, l1), pack_bf(l2, l3));
    }
    __syncthreads();

    // A tile, embed half: k 128..255, broadcast across rows
    for (int idx = tid; idx < MTILE * 32; idx += NTHREADS) {
        int r = idx >> 5, kq = idx & 31, k = 128 + kq * 4;
        float4 v = *(const float4*)(sEmb + kq * 4);
        __nv_bfloat16 h0, l0, h1, l1, h2, l2, h3, l3;
        split_bf(v.x, h0, l0); split_bf(v.y, h1, l1);
        split_bf(v.z, h2, l2); split_bf(v.w, h3, l3);
        uint32_t off = offA(r, k);
        *(uint2*)(sm + SM_AHI + off) = make_uint2(pack_bf(h0, h1), pack_bf(h2, h3));
        *(uint2*)(sm + SM_ALO + off) = make_uint2(pack_bf(l0, l1), pack_bf(l2, l3));
    }
    __syncthreads();

    const int g   = lane >> 2;
    const int tig = lane & 3;

    // per-lane ldmatrix address offset (within a k-step block)
    uint32_t aoff;
    {
        int q = lane >> 3, rr = lane & 7;
        int row = wm * 16 + (q & 1) * 8 + rr;
        int khalf = q >> 1;
        aoff = (uint32_t)(row * 32 + (((khalf ^ ((row >> 2) & 1)) & 1) << 4));
    }

    float acc[8][4];

    // ===== Layer 1 =====
    gemm_layer(smb + SM_AHI, g_Bf, aoff, lane, wn, acc);
    __syncthreads();

    // epilogue 1: tanh(+b1) -> re-split into A smem
    {
        int rA = wm * 16 + g;
        int rB = rA + 8;
        #pragma unroll
        for (int nt = 0; nt < 8; nt++) {
            int c0 = wn * 64 + nt * 8 + tig * 2;
            float t0 = tanhf(acc[nt][0] + sB1[c0]);
            float t1 = tanhf(acc[nt][1] + sB1[c0 + 1]);
            float t2 = tanhf(acc[nt][2] + sB1[c0]);
            float t3 = tanhf(acc[nt][3] + sB1[c0 + 1]);
            __nv_bfloat16 h0, l0, h1, l1;
            split_bf(t0, h0, l0); split_bf(t1, h1, l1);
            uint32_t oA = offA(rA, c0);
            *(uint32_t*)(sm + SM_AHI + oA) = pack_bf(h0, h1);
            *(uint32_t*)(sm + SM_ALO + oA) = pack_bf(l0, l1);
            split_bf(t2, h0, l0); split_bf(t3, h1, l1);
            uint32_t oB = offA(rB, c0);
            *(uint32_t*)(sm + SM_AHI + oB) = pack_bf(h0, h1);
            *(uint32_t*)(sm + SM_ALO + oB) = pack_bf(l0, l1);
        }
    }
    __syncthreads();

    // ===== Layer 2 =====
    gemm_layer(smb + SM_AHI, g_Bf + 65536, aoff, lane, wn, acc);

    // epilogue 2: tanh(+b2), dot with W3, reduce
    float e[2][2];
    e[0][0] = e[0][1] = e[1][0] = e[1][1] = 0.f;

    #pragma unroll
    for (int nt = 0; nt < 8; nt++) {
        int c0 = wn * 64 + nt * 8 + tig * 2;
        float o0 = tanhf(acc[nt][0] + sB2[c0]);
        float o1 = tanhf(acc[nt][1] + sB2[c0 + 1]);
        float o2 = tanhf(acc[nt][2] + sB2[c0]);
        float o3 = tanhf(acc[nt][3] + sB2[c0 + 1]);
        float w00 = sW3[2 * c0],     w01 = sW3[2 * c0 + 1];
        float w10 = sW3[2 * c0 + 2], w11 = sW3[2 * c0 + 3];
        e[0][0] = fmaf(o0, w00, fmaf(o1, w10, e[0][0]));
        e[0][1] = fmaf(o0, w01, fmaf(o1, w11, e[0][1]));
        e[1][0] = fmaf(o2, w00, fmaf(o3, w10, e[1][0]));
        e[1][1] = fmaf(o2, w01, fmaf(o3, w11, e[1][1]));
    }
    #pragma unroll
    for (int off = 1; off <= 2; off <<= 1)
        #pragma unroll
        for (int hh = 0; hh < 2; hh++) {
            e[hh][0] += __shfl_xor_sync(0xffffffffu, e[hh][0], off);
            e[hh][1] += __shfl_xor_sync(0xffffffffu, e[hh][1], off);
        }
    if (tig == 0) {
        #pragma unroll
        for (int hh = 0; hh < 2; hh++) {
            int row = wm * 16 + g + hh * 8;
            sRed[wn * 128 + row * 2 + 0] = e[hh][0];
            sRed[wn * 128 + row * 2 + 1] = e[hh][1];
        }
    }
    __syncthreads();

    if (tid < 128) {
        int row  = tid >> 1;
        int comp = tid & 1;
        float s = sRed[row * 2 + comp] + sRed[128 + row * 2 + comp]
                + sRed[256 + row * 2 + comp] + sRed[384 + row * 2 + comp]
                + b3[comp];
        int rg = r0 + row;
        out[(size_t)(rg >> 8) * 512 + (size_t)(rg & 255) * 2 + comp] = s;
    }
}

extern "C" void kernel_launch(void* const* d_in, const int* in_sizes, int n_in,
                              void* d_out, int out_size) {
    const float* last = (const float*)d_in[0];
    const float* h    = (const float*)d_in[1];
    const float* We   = (const float*)d_in[2];
    const float* be   = (const float*)d_in[3];
    const float* W1   = (const float*)d_in[4];
    const float* b1   = (const float*)d_in[5];
    const float* W2   = (const float*)d_in[6];
    const float* b2   = (const float*)d_in[7];
    const float* W3   = (const float*)d_in[8];
    const float* b3   = (const float*)d_in[9];
    float* out = (float*)d_out;

    prep_weights<<<512, 256>>>(W1, W2);

    cudaFuncSetAttribute(fused_hmma_kernel,
                         cudaFuncAttributeMaxDynamicSharedMemorySize, SM_TOTAL);
    fused_hmma_kernel<<<NCTA, NTHREADS, SM_TOTAL>>>(last, h, We, be, b1, b2, W3, b3, out);
}

// round 12
// speedup vs baseline: 2.7815x; 1.3467x over previous
#include <cuda_runtime.h>
#include <cuda_bf16.h>
#include <stdint.h>
#include <math.h>

// ---------- problem constants ----------
#define NROWS    131072           // 512 graphs * 256 nodes
#define INDIM    128
#define HIDN     128
#define D2       256
#define MTILE    64               // rows per CTA
#define NCTA     (NROWS / MTILE)  // 2048
#define NTHREADS 512              // 16 warps: wm in {0..3}, wn in {0..3}

// ---------- smem layout (bytes) ----------
#define SM_AHI   0                // 32KB A hi
#define SM_ALO   32768            // 32KB A lo
#define SM_BST   65536            // 2 x 64KB B chunk buffers (hi 32KB | lo 32KB each)
#define SM_EMB   196608           // 128 f32
#define SM_B1    197120           // 256 f32
#define SM_B2    198144           // 256 f32
#define SM_W3    199168           // 512 f32
#define SM_RED   201216           // 512 f32
#define SM_TOTAL 203264

// B fragments in global scratch, coalesced layout (same as R7):
// u32 idx = ((((l*2+p)*16 + ks)*4 + wn)*4 + q)*128 + lane*4 + j
__device__ uint32_t g_Bf[131072];   // 512KB

static __device__ __forceinline__ uint32_t pack_bf(__nv_bfloat16 a, __nv_bfloat16 b) {
    return ((uint32_t)__bfloat16_as_ushort(b) << 16) | (uint32_t)__bfloat16_as_ushort(a);
}
static __device__ __forceinline__ void split_bf(float v, __nv_bfloat16& hi, __nv_bfloat16& lo) {
    hi = __float2bfloat16(v);
    lo = __float2bfloat16(v - __bfloat162float(hi));
}
static __device__ __forceinline__ uint32_t s2u(const void* p) {
    uint32_t a;
    asm("{ .reg .u64 t; cvta.to.shared.u64 t, %1; cvt.u32.u64 %0, t; }"
        : "=r"(a) : "l"(p));
    return a;
}

// ---------- prep: split W1/W2 into bf16 hi/lo fragments (coalesced layout) ----------
__global__ void prep_weights(const float* __restrict__ W1, const float* __restrict__ W2) {
    int i = blockIdx.x * blockDim.x + threadIdx.x;   // 0..131071
    int j    = i & 3;
    int lane = (i >> 2) & 31;
    int q    = (i >> 7) & 3;
    int wn   = (i >> 9) & 3;
    int ks   = (i >> 11) & 15;
    int p    = (i >> 15) & 1;
    int l    = i >> 16;
    int s   = q * 4 + j;
    int nt  = s >> 1;
    int reg = s & 1;
    int NT  = wn * 8 + nt;
    const float* W = l ? W2 : W1;
    int k0 = ks * 16 + (lane & 3) * 2 + reg * 8;
    int n  = NT * 8 + (lane >> 2);
    float v0 = W[k0 * 256 + n];
    float v1 = W[(k0 + 1) * 256 + n];
    __nv_bfloat16 h0, l0, h1, l1;
    split_bf(v0, h0, l0);
    split_bf(v1, h1, l1);
    g_Bf[i] = (p == 0) ? pack_bf(h0, h1) : pack_bf(l0, l1);
}

// ---------- asm wrappers ----------
static __device__ __forceinline__ void mma_bf16(float* d, const uint32_t* a,
                                                uint32_t b0, uint32_t b1) {
    asm volatile(
        "mma.sync.aligned.m16n8k16.row.col.f32.bf16.bf16.f32 "
        "{%0,%1,%2,%3}, {%4,%5,%6,%7}, {%8,%9}, {%0,%1,%2,%3};"
        : "+f"(d[0]), "+f"(d[1]), "+f"(d[2]), "+f"(d[3])
        : "r"(a[0]), "r"(a[1]), "r"(a[2]), "r"(a[3]), "r"(b0), "r"(b1));
}
static __device__ __forceinline__ void ldsm4(uint32_t* r, uint32_t saddr) {
    asm volatile("ldmatrix.sync.aligned.m8n8.x4.shared.b16 {%0,%1,%2,%3}, [%4];"
                 : "=r"(r[0]), "=r"(r[1]), "=r"(r[2]), "=r"(r[3]) : "r"(saddr));
}
static __device__ __forceinline__ void lds128(uint4& v, uint32_t saddr) {
    asm volatile("ld.shared.v4.u32 {%0,%1,%2,%3}, [%4];"
                 : "=r"(v.x), "=r"(v.y), "=r"(v.z), "=r"(v.w) : "r"(saddr));
}
static __device__ __forceinline__ void cp16(uint32_t dst, const void* src) {
    asm volatile("cp.async.cg.shared.global [%0], [%1], 16;"
                 :: "r"(dst), "l"(src) : "memory");
}
#define CP_COMMIT() asm volatile("cp.async.commit_group;" ::: "memory")
#define CP_WAIT(n)  asm volatile("cp.async.wait_group %0;" :: "n"(n) : "memory")

// A smem byte offset for (row r, k); k-halves (16B) swapped when r&4.
static __device__ __forceinline__ uint32_t offA(int r, int k) {
    uint32_t c = (uint32_t)(k & 15);
    uint32_t cp = (c + (uint32_t)((r & 4) << 1)) & 15u;
    return ((uint32_t)(k >> 4) << 11) + ((uint32_t)r << 5) + (cp << 1);
}

// ---------- main fused kernel ----------
__global__ __launch_bounds__(NTHREADS, 1)
void fused_hmma_kernel(const float* __restrict__ last,
                       const float* __restrict__ h,
                       const float* __restrict__ We,
                       const float* __restrict__ be,
                       const float* __restrict__ b1,
                       const float* __restrict__ b2,
                       const float* __restrict__ W3,
                       const float* __restrict__ b3,
                       float* __restrict__ out) {
    extern __shared__ char sm[];
    const uint32_t smb = s2u(sm);
    const int tid  = threadIdx.x;
    const int lane = tid & 31;
    const int wid  = tid >> 5;
    const int wm   = wid >> 2;
    const int wn   = wid & 3;
    const int r0   = blockIdx.x * MTILE;
    const int grp  = r0 >> 8;

    float* sEmb = (float*)(sm + SM_EMB);
    float* sB1  = (float*)(sm + SM_B1);
    float* sB2  = (float*)(sm + SM_B2);
    float* sW3  = (float*)(sm + SM_W3);
    float* sRed = (float*)(sm + SM_RED);

    // ---- prefetch chunks 0,1 immediately (B path independent of A build) ----
    // chunk cc: layer = cc>>2, kb = cc&3; 64KB (hi 32KB | lo 32KB)
    {
        const uint32_t* hsrc = g_Bf + 0 * 65536 + 0 * 8192;
        uint32_t dbase = smb + SM_BST + 0 * 65536;
        #pragma unroll
        for (int it = 0; it < 4; it++) {
            cp16(dbase + tid * 16 + it * 8192,          hsrc + tid * 4 + it * 2048);
            cp16(dbase + 32768 + tid * 16 + it * 8192,  hsrc + 32768 + tid * 4 + it * 2048);
        }
        CP_COMMIT();
        hsrc = g_Bf + 1 * 8192;
        dbase = smb + SM_BST + 1 * 65536;
        #pragma unroll
        for (int it = 0; it < 4; it++) {
            cp16(dbase + tid * 16 + it * 8192,          hsrc + tid * 4 + it * 2048);
            cp16(dbase + 32768 + tid * 16 + it * 8192,  hsrc + 32768 + tid * 4 + it * 2048);
        }
        CP_COMMIT();
    }

    if (tid < 256) {
        sB1[tid] = b1[tid];
        sB2[tid] = b2[tid];
        sW3[tid]       = W3[tid];
        sW3[tid + 256] = W3[tid + 256];
    }

    if (tid < HIDN) {
        float acc0 = be[tid];
        const float* lrow = last + (size_t)grp * INDIM;
        #pragma unroll 4
        for (int k = 0; k < INDIM; k++)
            acc0 = fmaf(lrow[k], We[k * HIDN + tid], acc0);
        sEmb[tid] = acc0;
    }

    // A tile, h half
    for (int idx = tid; idx < MTILE * 32; idx += NTHREADS) {
        int r = idx >> 5, kq = idx & 31, k = kq * 4;
        float4 v = *(const float4*)(h + (size_t)(r0 + r) * HIDN + k);
        __nv_bfloat16 h0, l0, h1, l1, h2, l2, h3, l3;
        split_bf(v.x, h0, l0); split_bf(v.y, h1, l1);
        split_bf(v.z, h2, l2); split_bf(v.w, h3, l3);
        uint32_t off = offA(r, k);
        *(uint2*)(sm + SM_AHI + off) = make_uint2(pack_bf(h0, h1), pack_bf(h2, h3));
        *(uint2*)(sm + SM_ALO + off) = make_uint2(pack_bf(l0, l1), pack_bf(l2, l3));
    }
    __syncthreads();

    // A tile, embed half (broadcast)
    for (int idx = tid; idx < MTILE * 32; idx += NTHREADS) {
        int r = idx >> 5, kq = idx & 31, k = 128 + kq * 4;
        float4 v = *(const float4*)(sEmb + kq * 4);
        __nv_bfloat16 h0, l0, h1, l1, h2, l2, h3, l3;
        split_bf(v.x, h0, l0); split_bf(v.y, h1, l1);
        split_bf(v.z, h2, l2); split_bf(v.w, h3, l3);
        uint32_t off = offA(r, k);
        *(uint2*)(sm + SM_AHI + off) = make_uint2(pack_bf(h0, h1), pack_bf(h2, h3));
        *(uint2*)(sm + SM_ALO + off) = make_uint2(pack_bf(l0, l1), pack_bf(l2, l3));
    }

    const int g   = lane >> 2;
    const int tig = lane & 3;

    uint32_t aoff;
    {
        int q = lane >> 3, rr = lane & 7;
        int row = wm * 16 + (q & 1) * 8 + rr;
        int khalf = q >> 1;
        aoff = (uint32_t)(row * 32 + (((khalf ^ ((row >> 2) & 1)) & 1) << 4));
    }

    float acc[8][4];
    const uint32_t bfix = (uint32_t)wn * 2048 + (uint32_t)lane * 16;

    // ---- main pipeline: 8 chunks (layer = cc>>2), double-buffered ----
    #pragma unroll 1
    for (int cc = 0; cc < 8; cc++) {
        if (cc == 7) { CP_WAIT(0); } else { CP_WAIT(1); }
        __syncthreads();   // chunk cc data visible to all; also orders A writes/reads

        if ((cc & 3) == 0) {
            #pragma unroll
            for (int nt = 0; nt < 8; nt++)
                #pragma unroll
                for (int c = 0; c < 4; c++)
                    acc[nt][c] = 0.f;
        }

        const uint32_t bufb = smb + SM_BST + (uint32_t)(cc & 1) * 65536 + bfix;
        #pragma unroll
        for (int ksl = 0; ksl < 4; ksl++) {
            union { uint4 q[4]; uint32_t b[16]; } BH, BL;
            uint32_t bb = bufb + (uint32_t)ksl * 8192;
            #pragma unroll
            for (int i = 0; i < 4; i++) {
                lds128(BH.q[i], bb + (uint32_t)i * 512);
                lds128(BL.q[i], bb + 32768 + (uint32_t)i * 512);
            }
            int ks = (cc & 3) * 4 + ksl;
            uint32_t aH[4], aL[4];
            uint32_t abase = smb + SM_AHI + ((uint32_t)ks << 11) + aoff;
            ldsm4(aH, abase);
            ldsm4(aL, abase + 32768);

            #pragma unroll
            for (int nt = 0; nt < 8; nt++)
                mma_bf16(acc[nt], aH, BH.b[nt * 2], BH.b[nt * 2 + 1]);
            #pragma unroll
            for (int nt = 0; nt < 8; nt++)
                mma_bf16(acc[nt], aH, BL.b[nt * 2], BL.b[nt * 2 + 1]);
            #pragma unroll
            for (int nt = 0; nt < 8; nt++)
                mma_bf16(acc[nt], aL, BH.b[nt * 2], BH.b[nt * 2 + 1]);
        }
        __syncthreads();   // all reads of buffer (cc&1) done before refill

        if (cc < 6) {
            int nc = cc + 2;
            const uint32_t* hsrc = g_Bf + (nc >> 2) * 65536 + (nc & 3) * 8192;
            uint32_t dbase = smb + SM_BST + (uint32_t)(nc & 1) * 65536;
            #pragma unroll
            for (int it = 0; it < 4; it++) {
                cp16(dbase + tid * 16 + it * 8192,         hsrc + tid * 4 + it * 2048);
                cp16(dbase + 32768 + tid * 16 + it * 8192, hsrc + 32768 + tid * 4 + it * 2048);
            }
            CP_COMMIT();
        }

        if (cc == 3) {
            // ===== epilogue 1: tanh(+b1) -> re-split into A smem =====
            int rA = wm * 16 + g;
            int rB = rA + 8;
            #pragma unroll
            for (int nt = 0; nt < 8; nt++) {
                int c0 = wn * 64 + nt * 8 + tig * 2;
                float t0 = tanhf(acc[nt][0] + sB1[c0]);
                float t1 = tanhf(acc[nt][1] + sB1[c0 + 1]);
                float t2 = tanhf(acc[nt][2] + sB1[c0]);
                float t3 = tanhf(acc[nt][3] + sB1[c0 + 1]);
                __nv_bfloat16 h0, l0, h1, l1;
                split_bf(t0, h0, l0); split_bf(t1, h1, l1);
                uint32_t oA = offA(rA, c0);
                *(uint32_t*)(sm + SM_AHI + oA) = pack_bf(h0, h1);
                *(uint32_t*)(sm + SM_ALO + oA) = pack_bf(l0, l1);
                split_bf(t2, h0, l0); split_bf(t3, h1, l1);
                uint32_t oB = offA(rB, c0);
                *(uint32_t*)(sm + SM_AHI + oB) = pack_bf(h0, h1);
                *(uint32_t*)(sm + SM_ALO + oB) = pack_bf(l0, l1);
            }
            // next iteration's leading __syncthreads orders these A writes
        }
    }

    // ===== epilogue 2: tanh(+b2), dot with W3, reduce =====
    float e[2][2];
    e[0][0] = e[0][1] = e[1][0] = e[1][1] = 0.f;

    #pragma unroll
    for (int nt = 0; nt < 8; nt++) {
        int c0 = wn * 64 + nt * 8 + tig * 2;
        float o0 = tanhf(acc[nt][0] + sB2[c0]);
        float o1 = tanhf(acc[nt][1] + sB2[c0 + 1]);
        float o2 = tanhf(acc[nt][2] + sB2[c0]);
        float o3 = tanhf(acc[nt][3] + sB2[c0 + 1]);
        float w00 = sW3[2 * c0],     w01 = sW3[2 * c0 + 1];
        float w10 = sW3[2 * c0 + 2], w11 = sW3[2 * c0 + 3];
        e[0][0] = fmaf(o0, w00, fmaf(o1, w10, e[0][0]));
        e[0][1] = fmaf(o0, w01, fmaf(o1, w11, e[0][1]));
        e[1][0] = fmaf(o2, w00, fmaf(o3, w10, e[1][0]));
        e[1][1] = fmaf(o2, w01, fmaf(o3, w11, e[1][1]));
    }
    #pragma unroll
    for (int off = 1; off <= 2; off <<= 1)
        #pragma unroll
        for (int hh = 0; hh < 2; hh++) {
            e[hh][0] += __shfl_xor_sync(0xffffffffu, e[hh][0], off);
            e[hh][1] += __shfl_xor_sync(0xffffffffu, e[hh][1], off);
        }
    if (tig == 0) {
        #pragma unroll
        for (int hh = 0; hh < 2; hh++) {
            int row = wm * 16 + g + hh * 8;
            sRed[wn * 128 + row * 2 + 0] = e[hh][0];
            sRed[wn * 128 + row * 2 + 1] = e[hh][1];
        }
    }
    __syncthreads();

    if (tid < 128) {
        int row  = tid >> 1;
        int comp = tid & 1;
        float s = sRed[row * 2 + comp] + sRed[128 + row * 2 + comp]
                + sRed[256 + row * 2 + comp] + sRed[384 + row * 2 + comp]
                + b3[comp];
        int rg = r0 + row;
        out[(size_t)(rg >> 8) * 512 + (size_t)(rg & 255) * 2 + comp] = s;
    }
}

extern "C" void kernel_launch(void* const* d_in, const int* in_sizes, int n_in,
                              void* d_out, int out_size) {
    const float* last = (const float*)d_in[0];
    const float* h    = (const float*)d_in[1];
    const float* We   = (const float*)d_in[2];
    const float* be   = (const float*)d_in[3];
    const float* W1   = (const float*)d_in[4];
    const float* b1   = (const float*)d_in[5];
    const float* W2   = (const float*)d_in[6];
    const float* b2   = (const float*)d_in[7];
    const float* W3   = (const float*)d_in[8];
    const float* b3   = (const float*)d_in[9];
    float* out = (float*)d_out;

    prep_weights<<<512, 256>>>(W1, W2);

    cudaFuncSetAttribute(fused_hmma_kernel,
                         cudaFuncAttributeMaxDynamicSharedMemorySize, SM_TOTAL);
    fused_hmma_kernel<<<NCTA, NTHREADS, SM_TOTAL>>>(last, h, We, be, b1, b2, W3, b3, out);
}

// round 13
// speedup vs baseline: 2.7936x; 1.0044x over previous
#include <cuda_runtime.h>
#include <cuda_bf16.h>
#include <stdint.h>
#include <math.h>

// ---------- problem constants ----------
#define NROWS    131072           // 512 graphs * 256 nodes
#define INDIM    128
#define HIDN     128
#define D2       256
#define MTILE    64               // rows per CTA
#define NCTA     (NROWS / MTILE)  // 2048
#define NTHREADS 512              // 16 warps: wm2 in {0,1} (32-row), wn2 in {0..7} (32-col)

// ---------- smem layout (bytes) ----------
#define SM_AHI   0                // 32KB A hi
#define SM_ALO   32768            // 32KB A lo
#define SM_BST   65536            // 2 x 64KB B chunk buffers (hi 32KB | lo 32KB each)
#define SM_EMB   196608           // 128 f32
#define SM_B1    197120           // 256 f32
#define SM_B2    198144           // 256 f32
#define SM_W3    199168           // 512 f32
#define SM_RED   201216           // 8*64*2 f32 = 4KB
#define SM_TOTAL 205312

// B fragments in global scratch, coalesced layout (same as R7/R12):
// u32 idx = ((((l*2+p)*16 + ks)*4 + wn)*4 + q)*128 + lane*4 + j
__device__ uint32_t g_Bf[131072];   // 512KB

static __device__ __forceinline__ uint32_t pack_bf(__nv_bfloat16 a, __nv_bfloat16 b) {
    return ((uint32_t)__bfloat16_as_ushort(b) << 16) | (uint32_t)__bfloat16_as_ushort(a);
}
static __device__ __forceinline__ void split_bf(float v, __nv_bfloat16& hi, __nv_bfloat16& lo) {
    hi = __float2bfloat16(v);
    lo = __float2bfloat16(v - __bfloat162float(hi));
}
static __device__ __forceinline__ uint32_t s2u(const void* p) {
    uint32_t a;
    asm("{ .reg .u64 t; cvta.to.shared.u64 t, %1; cvt.u32.u64 %0, t; }"
        : "=r"(a) : "l"(p));
    return a;
}

// ---------- prep: split W1/W2 into bf16 hi/lo fragments (coalesced layout) ----------
__global__ void prep_weights(const float* __restrict__ W1, const float* __restrict__ W2) {
    int i = blockIdx.x * blockDim.x + threadIdx.x;   // 0..131071
    int j    = i & 3;
    int lane = (i >> 2) & 31;
    int q    = (i >> 7) & 3;
    int wn   = (i >> 9) & 3;
    int ks   = (i >> 11) & 15;
    int p    = (i >> 15) & 1;
    int l    = i >> 16;
    int s   = q * 4 + j;
    int nt  = s >> 1;
    int reg = s & 1;
    int NT  = wn * 8 + nt;
    const float* W = l ? W2 : W1;
    int k0 = ks * 16 + (lane & 3) * 2 + reg * 8;
    int n  = NT * 8 + (lane >> 2);
    float v0 = W[k0 * 256 + n];
    float v1 = W[(k0 + 1) * 256 + n];
    __nv_bfloat16 h0, l0, h1, l1;
    split_bf(v0, h0, l0);
    split_bf(v1, h1, l1);
    g_Bf[i] = (p == 0) ? pack_bf(h0, h1) : pack_bf(l0, l1);
}

// ---------- asm wrappers ----------
static __device__ __forceinline__ void mma_bf16(float* d, const uint32_t* a,
                                                uint32_t b0, uint32_t b1) {
    asm volatile(
        "mma.sync.aligned.m16n8k16.row.col.f32.bf16.bf16.f32 "
        "{%0,%1,%2,%3}, {%4,%5,%6,%7}, {%8,%9}, {%0,%1,%2,%3};"
        : "+f"(d[0]), "+f"(d[1]), "+f"(d[2]), "+f"(d[3])
        : "r"(a[0]), "r"(a[1]), "r"(a[2]), "r"(a[3]), "r"(b0), "r"(b1));
}
static __device__ __forceinline__ void ldsm4(uint32_t* r, uint32_t saddr) {
    asm volatile("ldmatrix.sync.aligned.m8n8.x4.shared.b16 {%0,%1,%2,%3}, [%4];"
                 : "=r"(r[0]), "=r"(r[1]), "=r"(r[2]), "=r"(r[3]) : "r"(saddr));
}
static __device__ __forceinline__ void lds128(uint4& v, uint32_t saddr) {
    asm volatile("ld.shared.v4.u32 {%0,%1,%2,%3}, [%4];"
                 : "=r"(v.x), "=r"(v.y), "=r"(v.z), "=r"(v.w) : "r"(saddr));
}
static __device__ __forceinline__ void cp16(uint32_t dst, const void* src) {
    asm volatile("cp.async.cg.shared.global [%0], [%1], 16;"
                 :: "r"(dst), "l"(src) : "memory");
}
#define CP_COMMIT() asm volatile("cp.async.commit_group;" ::: "memory")
#define CP_WAIT(n)  asm volatile("cp.async.wait_group %0;" :: "n"(n) : "memory")

// A smem byte offset for (row r, k); k-halves (16B) swapped when r&4.
static __device__ __forceinline__ uint32_t offA(int r, int k) {
    uint32_t c = (uint32_t)(k & 15);
    uint32_t cp = (c + (uint32_t)((r & 4) << 1)) & 15u;
    return ((uint32_t)(k >> 4) << 11) + ((uint32_t)r << 5) + (cp << 1);
}

// ---------- main fused kernel ----------
__global__ __launch_bounds__(NTHREADS, 1)
void fused_hmma_kernel(const float* __restrict__ last,
                       const float* __restrict__ h,
                       const float* __restrict__ We,
                       const float* __restrict__ be,
                       const float* __restrict__ b1,
                       const float* __restrict__ b2,
                       const float* __restrict__ W3,
                       const float* __restrict__ b3,
                       float* __restrict__ out) {
    extern __shared__ char sm[];
    const uint32_t smb = s2u(sm);
    const int tid  = threadIdx.x;
    const int lane = tid & 31;
    const int wid  = tid >> 5;
    const int wm2  = wid >> 3;       // 0..1  (32-row block)
    const int wn2  = wid & 7;        // 0..7  (32-col slice)
    const int wrot = wid & 3;        // ks rotation within chunk
    const int r0   = blockIdx.x * MTILE;
    const int grp  = r0 >> 8;

    float* sEmb = (float*)(sm + SM_EMB);
    float* sB1  = (float*)(sm + SM_B1);
    float* sB2  = (float*)(sm + SM_B2);
    float* sW3  = (float*)(sm + SM_W3);
    float* sRed = (float*)(sm + SM_RED);

    // ---- prefetch chunks 0,1 immediately ----
    {
        const uint32_t* hsrc = g_Bf;
        uint32_t dbase = smb + SM_BST;
        #pragma unroll
        for (int it = 0; it < 4; it++) {
            cp16(dbase + tid * 16 + it * 8192,          hsrc + tid * 4 + it * 2048);
            cp16(dbase + 32768 + tid * 16 + it * 8192,  hsrc + 32768 + tid * 4 + it * 2048);
        }
        CP_COMMIT();
        hsrc = g_Bf + 8192;
        dbase = smb + SM_BST + 65536;
        #pragma unroll
        for (int it = 0; it < 4; it++) {
            cp16(dbase + tid * 16 + it * 8192,          hsrc + tid * 4 + it * 2048);
            cp16(dbase + 32768 + tid * 16 + it * 8192,  hsrc + 32768 + tid * 4 + it * 2048);
        }
        CP_COMMIT();
    }

    if (tid < 256) {
        sB1[tid] = b1[tid];
        sB2[tid] = b2[tid];
        sW3[tid]       = W3[tid];
        sW3[tid + 256] = W3[tid + 256];
    }

    if (tid < HIDN) {
        float acc0 = be[tid];
        const float* lrow = last + (size_t)grp * INDIM;
        #pragma unroll 4
        for (int k = 0; k < INDIM; k++)
            acc0 = fmaf(lrow[k], We[k * HIDN + tid], acc0);
        sEmb[tid] = acc0;
    }

    // A tile, h half
    for (int idx = tid; idx < MTILE * 32; idx += NTHREADS) {
        int r = idx >> 5, kq = idx & 31, k = kq * 4;
        float4 v = *(const float4*)(h + (size_t)(r0 + r) * HIDN + k);
        __nv_bfloat16 h0, l0, h1, l1, h2, l2, h3, l3;
        split_bf(v.x, h0, l0); split_bf(v.y, h1, l1);
        split_bf(v.z, h2, l2); split_bf(v.w, h3, l3);
        uint32_t off = offA(r, k);
        *(uint2*)(sm + SM_AHI + off) = make_uint2(pack_bf(h0, h1), pack_bf(h2, h3));
        *(uint2*)(sm + SM_ALO + off) = make_uint2(pack_bf(l0, l1), pack_bf(l2, l3));
    }
    __syncthreads();

    // A tile, embed half (broadcast)
    for (int idx = tid; idx < MTILE * 32; idx += NTHREADS) {
        int r = idx >> 5, kq = idx & 31, k = 128 + kq * 4;
        float4 v = *(const float4*)(sEmb + kq * 4);
        __nv_bfloat16 h0, l0, h1, l1, h2, l2, h3, l3;
        split_bf(v.x, h0, l0); split_bf(v.y, h1, l1);
        split_bf(v.z, h2, l2); split_bf(v.w, h3, l3);
        uint32_t off = offA(r, k);
        *(uint2*)(sm + SM_AHI + off) = make_uint2(pack_bf(h0, h1), pack_bf(h2, h3));
        *(uint2*)(sm + SM_ALO + off) = make_uint2(pack_bf(l0, l1), pack_bf(l2, l3));
    }

    const int g   = lane >> 2;
    const int tig = lane & 3;

    // per-lane ldmatrix offset within a 16-row block
    uint32_t laneoff;
    {
        int q = lane >> 3, rr = lane & 7;
        laneoff = (uint32_t)(((q & 1) * 8 + rr) * 32 +
                             ((((q >> 1) ^ (rr >> 2)) & 1) << 4));
    }
    // A row-block bases for mt=0,1 (bytes)
    const uint32_t abm0 = (uint32_t)((wm2 * 32 + 0) * 32) + laneoff;
    const uint32_t abm1 = (uint32_t)((wm2 * 32 + 16) * 32) + laneoff;

    // B per-warp fixed offset inside a chunk buffer
    const uint32_t bfix = (uint32_t)(wn2 >> 1) * 2048 + (uint32_t)(wn2 & 1) * 1024
                        + (uint32_t)lane * 16;

    float acc[2][4][4];

    // ---- main pipeline: 8 chunks (layer = cc>>2), double-buffered ----
    #pragma unroll 1
    for (int cc = 0; cc < 8; cc++) {
        if (cc == 7) { CP_WAIT(0); } else { CP_WAIT(1); }
        __syncthreads();

        if ((cc & 3) == 0) {
            #pragma unroll
            for (int mt = 0; mt < 2; mt++)
                #pragma unroll
                for (int nt = 0; nt < 4; nt++)
                    #pragma unroll
                    for (int c = 0; c < 4; c++)
                        acc[mt][nt][c] = 0.f;
        }

        const uint32_t bufb = smb + SM_BST + (uint32_t)(cc & 1) * 65536 + bfix;
        #pragma unroll
        for (int i = 0; i < 4; i++) {
            int ksl = (i + wrot) & 3;              // per-warp rotation: de-phase LDS vs MMA
            union { uint4 q[2]; uint32_t b[8]; } BH, BL;
            uint32_t bb = bufb + (uint32_t)ksl * 8192;
            lds128(BH.q[0], bb);
            lds128(BH.q[1], bb + 512);
            lds128(BL.q[0], bb + 32768);
            lds128(BL.q[1], bb + 32768 + 512);

            int ks = (cc & 3) * 4 + ksl;
            uint32_t aH[2][4], aL[2][4];
            uint32_t ab = smb + SM_AHI + ((uint32_t)ks << 11);
            ldsm4(aH[0], ab + abm0);
            ldsm4(aH[1], ab + abm1);
            ldsm4(aL[0], ab + 32768 + abm0);
            ldsm4(aL[1], ab + 32768 + abm1);

            #pragma unroll
            for (int mt = 0; mt < 2; mt++)
                #pragma unroll
                for (int nt = 0; nt < 4; nt++)
                    mma_bf16(acc[mt][nt], aH[mt], BH.b[nt * 2], BH.b[nt * 2 + 1]);
            #pragma unroll
            for (int mt = 0; mt < 2; mt++)
                #pragma unroll
                for (int nt = 0; nt < 4; nt++)
                    mma_bf16(acc[mt][nt], aH[mt], BL.b[nt * 2], BL.b[nt * 2 + 1]);
            #pragma unroll
            for (int mt = 0; mt < 2; mt++)
                #pragma unroll
                for (int nt = 0; nt < 4; nt++)
                    mma_bf16(acc[mt][nt], aL[mt], BH.b[nt * 2], BH.b[nt * 2 + 1]);
        }
        __syncthreads();   // all reads of buffer (cc&1) done before refill

        if (cc < 6) {
            int nc = cc + 2;
            const uint32_t* hsrc = g_Bf + (nc >> 2) * 65536 + (nc & 3) * 8192;
            uint32_t dbase = smb + SM_BST + (uint32_t)(nc & 1) * 65536;
            #pragma unroll
            for (int it = 0; it < 4; it++) {
                cp16(dbase + tid * 16 + it * 8192,         hsrc + tid * 4 + it * 2048);
                cp16(dbase + 32768 + tid * 16 + it * 8192, hsrc + 32768 + tid * 4 + it * 2048);
            }
            CP_COMMIT();
        }

        if (cc == 3) {
            // ===== epilogue 1: tanh(+b1) -> re-split into A smem =====
            #pragma unroll
            for (int mt = 0; mt < 2; mt++) {
                int rA = wm2 * 32 + mt * 16 + g;
                int rB = rA + 8;
                #pragma unroll
                for (int nt = 0; nt < 4; nt++) {
                    int c0 = wn2 * 32 + nt * 8 + tig * 2;
                    float t0 = tanhf(acc[mt][nt][0] + sB1[c0]);
                    float t1 = tanhf(acc[mt][nt][1] + sB1[c0 + 1]);
                    float t2 = tanhf(acc[mt][nt][2] + sB1[c0]);
                    float t3 = tanhf(acc[mt][nt][3] + sB1[c0 + 1]);
                    __nv_bfloat16 h0, l0, h1, l1;
                    split_bf(t0, h0, l0); split_bf(t1, h1, l1);
                    uint32_t oA = offA(rA, c0);
                    *(uint32_t*)(sm + SM_AHI + oA) = pack_bf(h0, h1);
                    *(uint32_t*)(sm + SM_ALO + oA) = pack_bf(l0, l1);
                    split_bf(t2, h0, l0); split_bf(t3, h1, l1);
                    uint32_t oB = offA(rB, c0);
                    *(uint32_t*)(sm + SM_AHI + oB) = pack_bf(h0, h1);
                    *(uint32_t*)(sm + SM_ALO + oB) = pack_bf(l0, l1);
                }
            }
            // next iteration's leading __syncthreads orders these A writes
        }
    }

    // ===== epilogue 2: tanh(+b2), dot with W3, reduce =====
    float e[2][2][2];   // [mt][rowhalf][comp]
    #pragma unroll
    for (int mt = 0; mt < 2; mt++)
        #pragma unroll
        for (int hh = 0; hh < 2; hh++) { e[mt][hh][0] = 0.f; e[mt][hh][1] = 0.f; }

    #pragma unroll
    for (int mt = 0; mt < 2; mt++)
        #pragma unroll
        for (int nt = 0; nt < 4; nt++) {
            int c0 = wn2 * 32 + nt * 8 + tig * 2;
            float o0 = tanhf(acc[mt][nt][0] + sB2[c0]);
            float o1 = tanhf(acc[mt][nt][1] + sB2[c0 + 1]);
            float o2 = tanhf(acc[mt][nt][2] + sB2[c0]);
            float o3 = tanhf(acc[mt][nt][3] + sB2[c0 + 1]);
            float w00 = sW3[2 * c0],     w01 = sW3[2 * c0 + 1];
            float w10 = sW3[2 * c0 + 2], w11 = sW3[2 * c0 + 3];
            e[mt][0][0] = fmaf(o0, w00, fmaf(o1, w10, e[mt][0][0]));
            e[mt][0][1] = fmaf(o0, w01, fmaf(o1, w11, e[mt][0][1]));
            e[mt][1][0] = fmaf(o2, w00, fmaf(o3, w10, e[mt][1][0]));
            e[mt][1][1] = fmaf(o2, w01, fmaf(o3, w11, e[mt][1][1]));
        }
    #pragma unroll
    for (int off = 1; off <= 2; off <<= 1)
        #pragma unroll
        for (int mt = 0; mt < 2; mt++)
            #pragma unroll
            for (int hh = 0; hh < 2; hh++) {
                e[mt][hh][0] += __shfl_xor_sync(0xffffffffu, e[mt][hh][0], off);
                e[mt][hh][1] += __shfl_xor_sync(0xffffffffu, e[mt][hh][1], off);
            }
    if (tig == 0) {
        #pragma unroll
        for (int mt = 0; mt < 2; mt++)
            #pragma unroll
            for (int hh = 0; hh < 2; hh++) {
                int row = wm2 * 32 + mt * 16 + g + hh * 8;
                sRed[wn2 * 128 + row * 2 + 0] = e[mt][hh][0];
                sRed[wn2 * 128 + row * 2 + 1] = e[mt][hh][1];
            }
    }
    __syncthreads();

    if (tid < 128) {
        int row  = tid >> 1;
        int comp = tid & 1;
        float s = b3[comp];
        #pragma unroll
        for (int w = 0; w < 8; w++)
            s += sRed[w * 128 + row * 2 + comp];
        int rg = r0 + row;
        out[(size_t)(rg >> 8) * 512 + (size_t)(rg & 255) * 2 + comp] = s;
    }
}

extern "C" void kernel_launch(void* const* d_in, const int* in_sizes, int n_in,
                              void* d_out, int out_size) {
    const float* last = (const float*)d_in[0];
    const float* h    = (const float*)d_in[1];
    const float* We   = (const float*)d_in[2];
    const float* be   = (const float*)d_in[3];
    const float* W1   = (const float*)d_in[4];
    const float* b1   = (const float*)d_in[5];
    const float* W2   = (const float*)d_in[6];
    const float* b2   = (const float*)d_in[7];
    const float* W3   = (const float*)d_in[8];
    const float* b3   = (const float*)d_in[9];
    float* out = (float*)d_out;

    prep_weights<<<512, 256>>>(W1, W2);

    cudaFuncSetAttribute(fused_hmma_kernel,
                         cudaFuncAttributeMaxDynamicSharedMemorySize, SM_TOTAL);
    fused_hmma_kernel<<<NCTA, NTHREADS, SM_TOTAL>>>(last, h, We, be, b1, b2, W3, b3, out);
}

// round 14
// speedup vs baseline: 3.4241x; 1.2257x over previous
#include <cuda_runtime.h>
#include <cuda_bf16.h>
#include <stdint.h>
#include <math.h>

// ---------- problem constants ----------
#define NROWS    131072           // 512 graphs * 256 nodes
#define INDIM    128
#define HIDN     128
#define D2       256
#define MTILE    32               // rows per CTA
#define NCTA     (NROWS / MTILE)  // 4096
#define NTHREADS 256              // 8 warps, each 32 rows x 32 cols

// ---------- smem layout (bytes) ----------
#define SM_AHI   0                // 16KB A hi  (32 rows x 256 k bf16)
#define SM_ALO   16384            // 16KB A lo
#define SM_BST   32768            // 2 x 32KB B chunk buffers (2 ks each: hi 16KB | lo 16KB)
#define SM_EMB   98304            // 128 f32
#define SM_B1    98816            // 256 f32
#define SM_B2    99840            // 256 f32
#define SM_W3    100864           // 512 f32
#define SM_RED   102912           // 8*32*2 f32 = 2KB
#define SM_TOTAL 104960           // <= 113664 for 2 CTAs/SM

// B fragments in global scratch, coalesced layout (same as R7/R12/R13):
// u32 idx = ((((l*2+p)*16 + ks)*4 + wn)*4 + q)*128 + lane*4 + j
__device__ uint32_t g_Bf[131072];   // 512KB

static __device__ __forceinline__ uint32_t pack_bf(__nv_bfloat16 a, __nv_bfloat16 b) {
    return ((uint32_t)__bfloat16_as_ushort(b) << 16) | (uint32_t)__bfloat16_as_ushort(a);
}
static __device__ __forceinline__ void split_bf(float v, __nv_bfloat16& hi, __nv_bfloat16& lo) {
    hi = __float2bfloat16(v);
    lo = __float2bfloat16(v - __bfloat162float(hi));
}
static __device__ __forceinline__ uint32_t s2u(const void* p) {
    uint32_t a;
    asm("{ .reg .u64 t; cvta.to.shared.u64 t, %1; cvt.u32.u64 %0, t; }"
        : "=r"(a) : "l"(p));
    return a;
}
// fast accurate tanh: 1 - 2/(2^(x*log2e*2) + 1); MUFU.EX2 + MUFU.RCP, err ~1e-6 abs
static __device__ __forceinline__ float fast_tanh(float x) {
    float e, r;
    asm("ex2.approx.f32 %0, %1;" : "=f"(e) : "f"(x * 2.8853900817779268f));
    asm("rcp.approx.f32 %0, %1;" : "=f"(r) : "f"(e + 1.0f));
    return fmaf(-2.0f, r, 1.0f);
}
// truncation split helpers: hi = top-16-bits-as-bf16 (1 PRMT per pair), lo = rn(v - hi)
static __device__ __forceinline__ uint32_t pack_hi_trunc(float a, float b) {
    uint32_t r;
    asm("prmt.b32 %0, %1, %2, 0x7632;" : "=r"(r)
        : "r"(__float_as_uint(a)), "r"(__float_as_uint(b)));
    return r;
}
static __device__ __forceinline__ float trunc_hi(float v) {
    return __uint_as_float(__float_as_uint(v) & 0xffff0000u);
}
static __device__ __forceinline__ uint32_t pack_lo(float a, float b) {
    uint32_t r;
    float la = a - trunc_hi(a);
    float lb = b - trunc_hi(b);
    asm("cvt.rn.bf16x2.f32 %0, %1, %2;" : "=r"(r) : "f"(lb), "f"(la));
    return r;
}

// ---------- prep: split W1/W2 into bf16 hi/lo fragments (coalesced layout) ----------
__global__ void prep_weights(const float* __restrict__ W1, const float* __restrict__ W2) {
    int i = blockIdx.x * blockDim.x + threadIdx.x;   // 0..131071
    int j    = i & 3;
    int lane = (i >> 2) & 31;
    int q    = (i >> 7) & 3;
    int wn   = (i >> 9) & 3;
    int ks   = (i >> 11) & 15;
    int p    = (i >> 15) & 1;
    int l    = i >> 16;
    int s   = q * 4 + j;
    int nt  = s >> 1;
    int reg = s & 1;
    int NT  = wn * 8 + nt;
    const float* W = l ? W2 : W1;
    int k0 = ks * 16 + (lane & 3) * 2 + reg * 8;
    int n  = NT * 8 + (lane >> 2);
    float v0 = W[k0 * 256 + n];
    float v1 = W[(k0 + 1) * 256 + n];
    __nv_bfloat16 h0, l0, h1, l1;
    split_bf(v0, h0, l0);
    split_bf(v1, h1, l1);
    g_Bf[i] = (p == 0) ? pack_bf(h0, h1) : pack_bf(l0, l1);
}

// ---------- asm wrappers ----------
static __device__ __forceinline__ void mma_bf16(float* d, const uint32_t* a,
                                                uint32_t b0, uint32_t b1) {
    asm volatile(
        "mma.sync.aligned.m16n8k16.row.col.f32.bf16.bf16.f32 "
        "{%0,%1,%2,%3}, {%4,%5,%6,%7}, {%8,%9}, {%0,%1,%2,%3};"
        : "+f"(d[0]), "+f"(d[1]), "+f"(d[2]), "+f"(d[3])
        : "r"(a[0]), "r"(a[1]), "r"(a[2]), "r"(a[3]), "r"(b0), "r"(b1));
}
static __device__ __forceinline__ void ldsm4(uint32_t* r, uint32_t saddr) {
    asm volatile("ldmatrix.sync.aligned.m8n8.x4.shared.b16 {%0,%1,%2,%3}, [%4];"
                 : "=r"(r[0]), "=r"(r[1]), "=r"(r[2]), "=r"(r[3]) : "r"(saddr));
}
static __device__ __forceinline__ void lds128(uint4& v, uint32_t saddr) {
    asm volatile("ld.shared.v4.u32 {%0,%1,%2,%3}, [%4];"
                 : "=r"(v.x), "=r"(v.y), "=r"(v.z), "=r"(v.w) : "r"(saddr));
}
static __device__ __forceinline__ void cp16(uint32_t dst, const void* src) {
    asm volatile("cp.async.cg.shared.global [%0], [%1], 16;"
                 :: "r"(dst), "l"(src) : "memory");
}
#define CP_COMMIT() asm volatile("cp.async.commit_group;" ::: "memory")
#define CP_WAIT(n)  asm volatile("cp.async.wait_group %0;" :: "n"(n) : "memory")

// A smem byte offset for (row r 0..31, k); k-halves (16B) swapped when r&4.
// per-ks block = 32 rows * 32B = 1KB
static __device__ __forceinline__ uint32_t offA(int r, int k) {
    uint32_t c = (uint32_t)(k & 15);
    uint32_t cp = (c + (uint32_t)((r & 4) << 1)) & 15u;
    return ((uint32_t)(k >> 4) << 10) + ((uint32_t)r << 5) + (cp << 1);
}

// ---------- main fused kernel ----------
__global__ __launch_bounds__(NTHREADS, 2)
void fused_hmma_kernel(const float* __restrict__ last,
                       const float* __restrict__ h,
                       const float* __restrict__ We,
                       const float* __restrict__ be,
                       const float* __restrict__ b1,
                       const float* __restrict__ b2,
                       const float* __restrict__ W3,
                       const float* __restrict__ b3,
                       float* __restrict__ out) {
    extern __shared__ char sm[];
    const uint32_t smb = s2u(sm);
    const int tid  = threadIdx.x;
    const int lane = tid & 31;
    const int wn2  = tid >> 5;       // warp id = 32-col slice, 0..7
    const int wrot = wn2 & 1;        // ks de-phase within 2-ks chunk
    const int r0   = blockIdx.x * MTILE;
    const int grp  = r0 >> 8;

    float* sEmb = (float*)(sm + SM_EMB);
    float* sB1  = (float*)(sm + SM_B1);
    float* sB2  = (float*)(sm + SM_B2);
    float* sW3  = (float*)(sm + SM_W3);
    float* sRed = (float*)(sm + SM_RED);

    // ---- prefetch chunks 0,1 (2 ks each: hi 16KB | lo 16KB) ----
    #pragma unroll
    for (int c0 = 0; c0 < 2; c0++) {
        const uint32_t* hsrc = g_Bf + c0 * 4096;     // layer0, ks pair c0
        uint32_t dbase = smb + SM_BST + (uint32_t)c0 * 32768;
        #pragma unroll
        for (int it = 0; it < 4; it++) {
            cp16(dbase + tid * 16 + it * 4096,          hsrc + tid * 4 + it * 1024);
            cp16(dbase + 16384 + tid * 16 + it * 4096,  hsrc + 32768 + tid * 4 + it * 1024);
        }
        CP_COMMIT();
    }

    sB1[tid] = b1[tid];
    sB2[tid] = b2[tid];
    sW3[tid]       = W3[tid];
    sW3[tid + 256] = W3[tid + 256];

    if (tid < HIDN) {
        float acc0 = be[tid];
        const float* lrow = last + (size_t)grp * INDIM;
        #pragma unroll 4
        for (int k = 0; k < INDIM; k++)
            acc0 = fmaf(lrow[k], We[k * HIDN + tid], acc0);
        sEmb[tid] = acc0;
    }

    // A tile, h half: 32 rows x 128 k (4 iters/thread)
    #pragma unroll
    for (int it = 0; it < 4; it++) {
        int idx = tid + it * NTHREADS;
        int r = idx >> 5, kq = idx & 31, k = kq * 4;
        float4 v = *(const float4*)(h + (size_t)(r0 + r) * HIDN + k);
        uint32_t off = offA(r, k);
        *(uint2*)(sm + SM_AHI + off) = make_uint2(pack_hi_trunc(v.x, v.y), pack_hi_trunc(v.z, v.w));
        *(uint2*)(sm + SM_ALO + off) = make_uint2(pack_lo(v.x, v.y),       pack_lo(v.z, v.w));
    }
    __syncthreads();   // sEmb ready

    // A tile, embed half: k 128..255, broadcast across rows
    #pragma unroll
    for (int it = 0; it < 4; it++) {
        int idx = tid + it * NTHREADS;
        int r = idx >> 5, kq = idx & 31, k = 128 + kq * 4;
        float4 v = *(const float4*)(sEmb + kq * 4);
        uint32_t off = offA(r, k);
        *(uint2*)(sm + SM_AHI + off) = make_uint2(pack_hi_trunc(v.x, v.y), pack_hi_trunc(v.z, v.w));
        *(uint2*)(sm + SM_ALO + off) = make_uint2(pack_lo(v.x, v.y),       pack_lo(v.z, v.w));
    }
    // (mainloop's first __syncthreads orders these stores)

    const int g   = lane >> 2;
    const int tig = lane & 3;

    // per-lane ldmatrix offset within a 16-row block
    uint32_t laneoff;
    {
        int q = lane >> 3, rr = lane & 7;
        laneoff = (uint32_t)(((q & 1) * 8 + rr) * 32 +
                             ((((q >> 1) ^ (rr >> 2)) & 1) << 4));
    }
    const uint32_t abm0 = laneoff;          // rows 0..15
    const uint32_t abm1 = 512 + laneoff;    // rows 16..31

    // B per-warp fixed offset inside an 8KB per-ks block
    const uint32_t bfix = (uint32_t)(wn2 >> 1) * 2048 + (uint32_t)(wn2 & 1) * 1024
                        + (uint32_t)lane * 16;

    float acc[2][4][4];

    // ---- main pipeline: 16 chunks of 2 ks (layer = cc>>3), double-buffered ----
    #pragma unroll 1
    for (int cc = 0; cc < 16; cc++) {
        if (cc == 15) { CP_WAIT(0); } else { CP_WAIT(1); }
        __syncthreads();

        if ((cc & 7) == 0) {
            #pragma unroll
            for (int mt = 0; mt < 2; mt++)
                #pragma unroll
                for (int nt = 0; nt < 4; nt++)
                    #pragma unroll
                    for (int c = 0; c < 4; c++)
                        acc[mt][nt][c] = 0.f;
        }

        const uint32_t bufb = smb + SM_BST + (uint32_t)(cc & 1) * 32768;
        #pragma unroll
        for (int i = 0; i < 2; i++) {
            int ksl = (i + wrot) & 1;              // de-phase LDS vs MMA across warps
            union { uint4 q[2]; uint32_t b[8]; } BH, BL;
            uint32_t bbh = bufb + (uint32_t)ksl * 8192 + bfix;
            lds128(BH.q[0], bbh);
            lds128(BH.q[1], bbh + 512);
            lds128(BL.q[0], bbh + 16384);
            lds128(BL.q[1], bbh + 16384 + 512);

            int ks = (cc & 7) * 2 + ksl;
            uint32_t aH[2][4], aL[2][4];
            uint32_t ab = smb + SM_AHI + ((uint32_t)ks << 10);
            ldsm4(aH[0], ab + abm0);
            ldsm4(aH[1], ab + abm1);
            ldsm4(aL[0], ab + 16384 + abm0);
            ldsm4(aL[1], ab + 16384 + abm1);

            #pragma unroll
            for (int mt = 0; mt < 2; mt++)
                #pragma unroll
                for (int nt = 0; nt < 4; nt++)
                    mma_bf16(acc[mt][nt], aH[mt], BH.b[nt * 2], BH.b[nt * 2 + 1]);
            #pragma unroll
            for (int mt = 0; mt < 2; mt++)
                #pragma unroll
                for (int nt = 0; nt < 4; nt++)
                    mma_bf16(acc[mt][nt], aH[mt], BL.b[nt * 2], BL.b[nt * 2 + 1]);
            #pragma unroll
            for (int mt = 0; mt < 2; mt++)
                #pragma unroll
                for (int nt = 0; nt < 4; nt++)
                    mma_bf16(acc[mt][nt], aL[mt], BH.b[nt * 2], BH.b[nt * 2 + 1]);
        }
        __syncthreads();   // all reads of buffer (cc&1) done before refill

        if (cc < 14) {
            int nc = cc + 2;
            const uint32_t* hsrc = g_Bf + (nc >> 3) * 65536 + (nc & 7) * 4096;
            uint32_t dbase = smb + SM_BST + (uint32_t)(nc & 1) * 32768;
            #pragma unroll
            for (int it = 0; it < 4; it++) {
                cp16(dbase + tid * 16 + it * 4096,         hsrc + tid * 4 + it * 1024);
                cp16(dbase + 16384 + tid * 16 + it * 4096, hsrc + 32768 + tid * 4 + it * 1024);
            }
            CP_COMMIT();
        }

        if (cc == 7) {
            // ===== epilogue 1: tanh(+b1) -> re-split into A smem =====
            #pragma unroll
            for (int mt = 0; mt < 2; mt++) {
                int rA = mt * 16 + g;
                int rB = rA + 8;
                #pragma unroll
                for (int nt = 0; nt < 4; nt++) {
                    int c0 = wn2 * 32 + nt * 8 + tig * 2;
                    float t0 = fast_tanh(acc[mt][nt][0] + sB1[c0]);
                    float t1 = fast_tanh(acc[mt][nt][1] + sB1[c0 + 1]);
                    float t2 = fast_tanh(acc[mt][nt][2] + sB1[c0]);
                    float t3 = fast_tanh(acc[mt][nt][3] + sB1[c0 + 1]);
                    uint32_t oA = offA(rA, c0);
                    *(uint32_t*)(sm + SM_AHI + oA) = pack_hi_trunc(t0, t1);
                    *(uint32_t*)(sm + SM_ALO + oA) = pack_lo(t0, t1);
                    uint32_t oB = offA(rB, c0);
                    *(uint32_t*)(sm + SM_AHI + oB) = pack_hi_trunc(t2, t3);
                    *(uint32_t*)(sm + SM_ALO + oB) = pack_lo(t2, t3);
                }
            }
            // next iteration's leading __syncthreads orders these A writes
        }
    }

    // ===== epilogue 2: tanh(+b2), dot with W3, reduce =====
    float e[2][2][2];   // [mt][rowhalf][comp]
    #pragma unroll
    for (int mt = 0; mt < 2; mt++)
        #pragma unroll
        for (int hh = 0; hh < 2; hh++) { e[mt][hh][0] = 0.f; e[mt][hh][1] = 0.f; }

    #pragma unroll
    for (int mt = 0; mt < 2; mt++)
        #pragma unroll
        for (int nt = 0; nt < 4; nt++) {
            int c0 = wn2 * 32 + nt * 8 + tig * 2;
            float o0 = fast_tanh(acc[mt][nt][0] + sB2[c0]);
            float o1 = fast_tanh(acc[mt][nt][1] + sB2[c0 + 1]);
            float o2 = fast_tanh(acc[mt][nt][2] + sB2[c0]);
            float o3 = fast_tanh(acc[mt][nt][3] + sB2[c0 + 1]);
            float w00 = sW3[2 * c0],     w01 = sW3[2 * c0 + 1];
            float w10 = sW3[2 * c0 + 2], w11 = sW3[2 * c0 + 3];
            e[mt][0][0] = fmaf(o0, w00, fmaf(o1, w10, e[mt][0][0]));
            e[mt][0][1] = fmaf(o0, w01, fmaf(o1, w11, e[mt][0][1]));
            e[mt][1][0] = fmaf(o2, w00, fmaf(o3, w10, e[mt][1][0]));
            e[mt][1][1] = fmaf(o2, w01, fmaf(o3, w11, e[mt][1][1]));
        }
    #pragma unroll
    for (int off = 1; off <= 2; off <<= 1)
        #pragma unroll
        for (int mt = 0; mt < 2; mt++)
            #pragma unroll
            for (int hh = 0; hh < 2; hh++) {
                e[mt][hh][0] += __shfl_xor_sync(0xffffffffu, e[mt][hh][0], off);
                e[mt][hh][1] += __shfl_xor_sync(0xffffffffu, e[mt][hh][1], off);
            }
    if (tig == 0) {
        #pragma unroll
        for (int mt = 0; mt < 2; mt++)
            #pragma unroll
            for (int hh = 0; hh < 2; hh++) {
                int row = mt * 16 + g + hh * 8;
                sRed[wn2 * 64 + row * 2 + 0] = e[mt][hh][0];
                sRed[wn2 * 64 + row * 2 + 1] = e[mt][hh][1];
            }
    }
    __syncthreads();

    if (tid < 64) {
        int row  = tid >> 1;
        int comp = tid & 1;
        float s = b3[comp];
        #pragma unroll
        for (int w = 0; w < 8; w++)
            s += sRed[w * 64 + row * 2 + comp];
        int rg = r0 + row;
        out[(size_t)(rg >> 8) * 512 + (size_t)(rg & 255) * 2 + comp] = s;
    }
}

extern "C" void kernel_launch(void* const* d_in, const int* in_sizes, int n_in,
                              void* d_out, int out_size) {
    const float* last = (const float*)d_in[0];
    const float* h    = (const float*)d_in[1];
    const float* We   = (const float*)d_in[2];
    const float* be   = (const float*)d_in[3];
    const float* W1   = (const float*)d_in[4];
    const float* b1   = (const float*)d_in[5];
    const float* W2   = (const float*)d_in[6];
    const float* b2   = (const float*)d_in[7];
    const float* W3   = (const float*)d_in[8];
    const float* b3   = (const float*)d_in[9];
    float* out = (float*)d_out;

    prep_weights<<<512, 256>>>(W1, W2);

    cudaFuncSetAttribute(fused_hmma_kernel,
                         cudaFuncAttributeMaxDynamicSharedMemorySize, SM_TOTAL);
    fused_hmma_kernel<<<NCTA, NTHREADS, SM_TOTAL>>>(last, h, We, be, b1, b2, W3, b3, out);
}

// round 15
// speedup vs baseline: 4.1602x; 1.2150x over previous
#include <cuda_runtime.h>
#include <cuda_bf16.h>
#include <stdint.h>
#include <math.h>

// ---------- problem constants ----------
#define NROWS    131072           // 512 graphs * 256 nodes
#define INDIM    128
#define HIDN     128
#define D2       256
#define MTILE    32               // rows per CTA
#define NCTA     (NROWS / MTILE)  // 4096
#define NTHREADS 256              // 8 warps, each 32 rows x 32 cols

// ---------- smem layout (bytes) ----------
#define SM_AHI   0                // 16KB A hi  (32 rows x 256 k bf16)
#define SM_ALO   16384            // 16KB A lo
#define SM_BW    32768            // per-warp B rings: 8 warps x 8KB (4 bufs x (hi 1KB | lo 1KB))
#define SM_EMB   98304            // 128 f32
#define SM_B1    98816            // 256 f32
#define SM_B2    99840            // 256 f32
#define SM_W3    100864           // 512 f32
#define SM_RED   102912           // 8*32*2 f32 = 2KB
#define SM_TOTAL 104960           // <= 113664 for 2 CTAs/SM

// B fragments in global scratch, coalesced layout (same as R7..R14):
// u32 idx = ((((l*2+p)*16 + ks)*4 + wn)*4 + q)*128 + lane*4 + j
__device__ uint32_t g_Bf[131072];   // 512KB

static __device__ __forceinline__ uint32_t pack_bf(__nv_bfloat16 a, __nv_bfloat16 b) {
    return ((uint32_t)__bfloat16_as_ushort(b) << 16) | (uint32_t)__bfloat16_as_ushort(a);
}
static __device__ __forceinline__ void split_bf(float v, __nv_bfloat16& hi, __nv_bfloat16& lo) {
    hi = __float2bfloat16(v);
    lo = __float2bfloat16(v - __bfloat162float(hi));
}
static __device__ __forceinline__ uint32_t s2u(const void* p) {
    uint32_t a;
    asm("{ .reg .u64 t; cvta.to.shared.u64 t, %1; cvt.u32.u64 %0, t; }"
        : "=r"(a) : "l"(p));
    return a;
}
// fast accurate tanh: 1 - 2/(2^(x*2*log2e) + 1); MUFU.EX2 + MUFU.RCP
static __device__ __forceinline__ float fast_tanh(float x) {
    float e, r;
    asm("ex2.approx.f32 %0, %1;" : "=f"(e) : "f"(x * 2.8853900817779268f));
    asm("rcp.approx.f32 %0, %1;" : "=f"(r) : "f"(e + 1.0f));
    return fmaf(-2.0f, r, 1.0f);
}
// truncation split: hi-pair via PRMT, lo-pair via rn(v - hi)
static __device__ __forceinline__ uint32_t pack_hi_trunc(float a, float b) {
    uint32_t r;
    asm("prmt.b32 %0, %1, %2, 0x7632;" : "=r"(r)
        : "r"(__float_as_uint(a)), "r"(__float_as_uint(b)));
    return r;
}
static __device__ __forceinline__ float trunc_hi(float v) {
    return __uint_as_float(__float_as_uint(v) & 0xffff0000u);
}
static __device__ __forceinline__ uint32_t pack_lo(float a, float b) {
    uint32_t r;
    float la = a - trunc_hi(a);
    float lb = b - trunc_hi(b);
    asm("cvt.rn.bf16x2.f32 %0, %1, %2;" : "=r"(r) : "f"(lb), "f"(la));
    return r;
}

// ---------- prep: split W1/W2 into bf16 hi/lo fragments (coalesced layout) ----------
__global__ void prep_weights(const float* __restrict__ W1, const float* __restrict__ W2) {
    int i = blockIdx.x * blockDim.x + threadIdx.x;   // 0..131071
    int j    = i & 3;
    int lane = (i >> 2) & 31;
    int q    = (i >> 7) & 3;
    int wn   = (i >> 9) & 3;
    int ks   = (i >> 11) & 15;
    int p    = (i >> 15) & 1;
    int l    = i >> 16;
    int s   = q * 4 + j;
    int nt  = s >> 1;
    int reg = s & 1;
    int NT  = wn * 8 + nt;
    const float* W = l ? W2 : W1;
    int k0 = ks * 16 + (lane & 3) * 2 + reg * 8;
    int n  = NT * 8 + (lane >> 2);
    float v0 = W[k0 * 256 + n];
    float v1 = W[(k0 + 1) * 256 + n];
    __nv_bfloat16 h0, l0, h1, l1;
    split_bf(v0, h0, l0);
    split_bf(v1, h1, l1);
    g_Bf[i] = (p == 0) ? pack_bf(h0, h1) : pack_bf(l0, l1);
}

// ---------- asm wrappers ----------
static __device__ __forceinline__ void mma_bf16(float* d, const uint32_t* a,
                                                uint32_t b0, uint32_t b1) {
    asm volatile(
        "mma.sync.aligned.m16n8k16.row.col.f32.bf16.bf16.f32 "
        "{%0,%1,%2,%3}, {%4,%5,%6,%7}, {%8,%9}, {%0,%1,%2,%3};"
        : "+f"(d[0]), "+f"(d[1]), "+f"(d[2]), "+f"(d[3])
        : "r"(a[0]), "r"(a[1]), "r"(a[2]), "r"(a[3]), "r"(b0), "r"(b1));
}
static __device__ __forceinline__ void ldsm4(uint32_t* r, uint32_t saddr) {
    asm volatile("ldmatrix.sync.aligned.m8n8.x4.shared.b16 {%0,%1,%2,%3}, [%4];"
                 : "=r"(r[0]), "=r"(r[1]), "=r"(r[2]), "=r"(r[3]) : "r"(saddr));
}
static __device__ __forceinline__ void lds128(uint4& v, uint32_t saddr) {
    asm volatile("ld.shared.v4.u32 {%0,%1,%2,%3}, [%4];"
                 : "=r"(v.x), "=r"(v.y), "=r"(v.z), "=r"(v.w) : "r"(saddr));
}
static __device__ __forceinline__ void cp16(uint32_t dst, const void* src) {
    asm volatile("cp.async.cg.shared.global [%0], [%1], 16;"
                 :: "r"(dst), "l"(src) : "memory");
}
#define CP_COMMIT() asm volatile("cp.async.commit_group;" ::: "memory")
#define CP_WAIT(n)  asm volatile("cp.async.wait_group %0;" :: "n"(n) : "memory")

// A smem byte offset for (row r 0..31, k); k-halves (16B) swapped when r&4.
// per-ks block = 32 rows * 32B = 1KB
static __device__ __forceinline__ uint32_t offA(int r, int k) {
    uint32_t c = (uint32_t)(k & 15);
    uint32_t cp = (c + (uint32_t)((r & 4) << 1)) & 15u;
    return ((uint32_t)(k >> 4) << 10) + ((uint32_t)r << 5) + (cp << 1);
}

// ---------- main fused kernel ----------
__global__ __launch_bounds__(NTHREADS, 2)
void fused_hmma_kernel(const float* __restrict__ last,
                       const float* __restrict__ h,
                       const float* __restrict__ We,
                       const float* __restrict__ be,
                       const float* __restrict__ b1,
                       const float* __restrict__ b2,
                       const float* __restrict__ W3,
                       const float* __restrict__ b3,
                       float* __restrict__ out) {
    extern __shared__ char sm[];
    const uint32_t smb = s2u(sm);
    const int tid  = threadIdx.x;
    const int lane = tid & 31;
    const int wn2  = tid >> 5;       // warp id = 32-col slice, 0..7
    const int r0   = blockIdx.x * MTILE;
    const int grp  = r0 >> 8;

    float* sEmb = (float*)(sm + SM_EMB);
    float* sB1  = (float*)(sm + SM_B1);
    float* sB2  = (float*)(sm + SM_B2);
    float* sW3  = (float*)(sm + SM_W3);
    float* sRed = (float*)(sm + SM_RED);

    // per-warp B ring: warp slice of global ks-block = [wn2*1KB, +1KB)
    const uint32_t bufbase = smb + SM_BW + (uint32_t)wn2 * 8192 + (uint32_t)lane * 16;
    const uint32_t gwoff   = (uint32_t)wn2 * 256 + (uint32_t)lane * 4;   // u32 units

    // per-warp fetch of global ks index ksg (0..31; layer = ksg>>4) into ring slot ksg&3
    auto fetchB = [&](int ksg) {
        const uint32_t* srcH = g_Bf + (uint32_t)(((ksg >> 4) * 32 + (ksg & 15)) * 2048) + gwoff;
        uint32_t dst = bufbase + (uint32_t)(ksg & 3) * 2048;
        cp16(dst,         srcH);
        cp16(dst + 512,   srcH + 128);
        cp16(dst + 1024,  srcH + 32768);        // lo part (p=1): +16*2048 u32
        cp16(dst + 1536,  srcH + 32768 + 128);
        CP_COMMIT();
    };

    // ---- prologue: 3-deep per-warp prefetch, overlaps A build ----
    fetchB(0); fetchB(1); fetchB(2);

    sB1[tid] = b1[tid];
    sB2[tid] = b2[tid];
    sW3[tid]       = W3[tid];
    sW3[tid + 256] = W3[tid + 256];

    if (tid < HIDN) {
        float acc0 = be[tid];
        const float* lrow = last + (size_t)grp * INDIM;
        #pragma unroll 4
        for (int k = 0; k < INDIM; k++)
            acc0 = fmaf(lrow[k], We[k * HIDN + tid], acc0);
        sEmb[tid] = acc0;
    }

    // A tile, h half: 32 rows x 128 k
    #pragma unroll
    for (int it = 0; it < 4; it++) {
        int idx = tid + it * NTHREADS;
        int r = idx >> 5, kq = idx & 31, k = kq * 4;
        float4 v = *(const float4*)(h + (size_t)(r0 + r) * HIDN + k);
        uint32_t off = offA(r, k);
        *(uint2*)(sm + SM_AHI + off) = make_uint2(pack_hi_trunc(v.x, v.y), pack_hi_trunc(v.z, v.w));
        *(uint2*)(sm + SM_ALO + off) = make_uint2(pack_lo(v.x, v.y),       pack_lo(v.z, v.w));
    }
    __syncthreads();   // sEmb ready

    // A tile, embed half: k 128..255, broadcast across rows
    #pragma unroll
    for (int it = 0; it < 4; it++) {
        int idx = tid + it * NTHREADS;
        int r = idx >> 5, kq = idx & 31, k = 128 + kq * 4;
        float4 v = *(const float4*)(sEmb + kq * 4);
        uint32_t off = offA(r, k);
        *(uint2*)(sm + SM_AHI + off) = make_uint2(pack_hi_trunc(v.x, v.y), pack_hi_trunc(v.z, v.w));
        *(uint2*)(sm + SM_ALO + off) = make_uint2(pack_lo(v.x, v.y),       pack_lo(v.z, v.w));
    }
    __syncthreads();   // A tile complete before any warp's mainloop reads

    const int g   = lane >> 2;
    const int tig = lane & 3;

    // per-lane ldmatrix offset within a 16-row block
    uint32_t laneoff;
    {
        int q = lane >> 3, rr = lane & 7;
        laneoff = (uint32_t)(((q & 1) * 8 + rr) * 32 +
                             ((((q >> 1) ^ (rr >> 2)) & 1) << 4));
    }
    const uint32_t abm0 = laneoff;          // rows 0..15
    const uint32_t abm1 = 512 + laneoff;    // rows 16..31

    float acc[2][4][4];

    // ---- barrier-free mainloop: 32 global ks (layer = ksg>>4) ----
    #pragma unroll 1
    for (int ksg = 0; ksg < 32; ksg++) {
        if ((ksg & 15) == 0) {
            #pragma unroll
            for (int mt = 0; mt < 2; mt++)
                #pragma unroll
                for (int nt = 0; nt < 4; nt++)
                    #pragma unroll
                    for (int c = 0; c < 4; c++)
                        acc[mt][nt][c] = 0.f;
        }

        if (ksg <= 28) fetchB(ksg + 3);
        if (ksg < 29) { CP_WAIT(3); } else if (ksg == 29) { CP_WAIT(0); }

        // B fragments from this warp's private ring slot (lane reads its own cp.async data)
        union { uint4 q[2]; uint32_t b[8]; } BH, BL;
        uint32_t bb = bufbase + (uint32_t)(ksg & 3) * 2048;
        lds128(BH.q[0], bb);
        lds128(BH.q[1], bb + 512);
        lds128(BL.q[0], bb + 1024);
        lds128(BL.q[1], bb + 1536);

        // A fragments
        uint32_t aH[2][4], aL[2][4];
        uint32_t ab = smb + SM_AHI + ((uint32_t)(ksg & 15) << 10);
        ldsm4(aH[0], ab + abm0);
        ldsm4(aH[1], ab + abm1);
        ldsm4(aL[0], ab + 16384 + abm0);
        ldsm4(aL[1], ab + 16384 + abm1);

        #pragma unroll
        for (int mt = 0; mt < 2; mt++)
            #pragma unroll
            for (int nt = 0; nt < 4; nt++)
                mma_bf16(acc[mt][nt], aH[mt], BH.b[nt * 2], BH.b[nt * 2 + 1]);
        #pragma unroll
        for (int mt = 0; mt < 2; mt++)
            #pragma unroll
            for (int nt = 0; nt < 4; nt++)
                mma_bf16(acc[mt][nt], aH[mt], BL.b[nt * 2], BL.b[nt * 2 + 1]);
        #pragma unroll
        for (int mt = 0; mt < 2; mt++)
            #pragma unroll
            for (int nt = 0; nt < 4; nt++)
                mma_bf16(acc[mt][nt], aL[mt], BH.b[nt * 2], BH.b[nt * 2 + 1]);

        if (ksg == 15) {
            // ===== layer boundary: the ONLY CTA barriers in the mainloop =====
            __syncthreads();   // all warps done reading layer-1 A
            #pragma unroll
            for (int mt = 0; mt < 2; mt++) {
                int rA = mt * 16 + g;
                int rB = rA + 8;
                #pragma unroll
                for (int nt = 0; nt < 4; nt++) {
                    int c0 = wn2 * 32 + nt * 8 + tig * 2;
                    float t0 = fast_tanh(acc[mt][nt][0] + sB1[c0]);
                    float t1 = fast_tanh(acc[mt][nt][1] + sB1[c0 + 1]);
                    float t2 = fast_tanh(acc[mt][nt][2] + sB1[c0]);
                    float t3 = fast_tanh(acc[mt][nt][3] + sB1[c0 + 1]);
                    uint32_t oA = offA(rA, c0);
                    *(uint32_t*)(sm + SM_AHI + oA) = pack_hi_trunc(t0, t1);
                    *(uint32_t*)(sm + SM_ALO + oA) = pack_lo(t0, t1);
                    uint32_t oB = offA(rB, c0);
                    *(uint32_t*)(sm + SM_AHI + oB) = pack_hi_trunc(t2, t3);
                    *(uint32_t*)(sm + SM_ALO + oB) = pack_lo(t2, t3);
                }
            }
            __syncthreads();   // layer-2 A visible to all warps
        }
    }

    // ===== epilogue 2: tanh(+b2), dot with W3, reduce =====
    float e[2][2][2];   // [mt][rowhalf][comp]
    #pragma unroll
    for (int mt = 0; mt < 2; mt++)
        #pragma unroll
        for (int hh = 0; hh < 2; hh++) { e[mt][hh][0] = 0.f; e[mt][hh][1] = 0.f; }

    #pragma unroll
    for (int mt = 0; mt < 2; mt++)
        #pragma unroll
        for (int nt = 0; nt < 4; nt++) {
            int c0 = wn2 * 32 + nt * 8 + tig * 2;
            float o0 = fast_tanh(acc[mt][nt][0] + sB2[c0]);
            float o1 = fast_tanh(acc[mt][nt][1] + sB2[c0 + 1]);
            float o2 = fast_tanh(acc[mt][nt][2] + sB2[c0]);
            float o3 = fast_tanh(acc[mt][nt][3] + sB2[c0 + 1]);
            float w00 = sW3[2 * c0],     w01 = sW3[2 * c0 + 1];
            float w10 = sW3[2 * c0 + 2], w11 = sW3[2 * c0 + 3];
            e[mt][0][0] = fmaf(o0, w00, fmaf(o1, w10, e[mt][0][0]));
            e[mt][0][1] = fmaf(o0, w01, fmaf(o1, w11, e[mt][0][1]));
            e[mt][1][0] = fmaf(o2, w00, fmaf(o3, w10, e[mt][1][0]));
            e[mt][1][1] = fmaf(o2, w01, fmaf(o3, w11, e[mt][1][1]));
        }
    #pragma unroll
    for (int off = 1; off <= 2; off <<= 1)
        #pragma unroll
        for (int mt = 0; mt < 2; mt++)
            #pragma unroll
            for (int hh = 0; hh < 2; hh++) {
                e[mt][hh][0] += __shfl_xor_sync(0xffffffffu, e[mt][hh][0], off);
                e[mt][hh][1] += __shfl_xor_sync(0xffffffffu, e[mt][hh][1], off);
            }
    if (tig == 0) {
        #pragma unroll
        for (int mt = 0; mt < 2; mt++)
            #pragma unroll
            for (int hh = 0; hh < 2; hh++) {
                int row = mt * 16 + g + hh * 8;
                sRed[wn2 * 64 + row * 2 + 0] = e[mt][hh][0];
                sRed[wn2 * 64 + row * 2 + 1] = e[mt][hh][1];
            }
    }
    __syncthreads();

    if (tid < 64) {
        int row  = tid >> 1;
        int comp = tid & 1;
        float s = b3[comp];
        #pragma unroll
        for (int w = 0; w < 8; w++)
            s += sRed[w * 64 + row * 2 + comp];
        int rg = r0 + row;
        out[(size_t)(rg >> 8) * 512 + (size_t)(rg & 255) * 2 + comp] = s;
    }
}

extern "C" void kernel_launch(void* const* d_in, const int* in_sizes, int n_in,
                              void* d_out, int out_size) {
    const float* last = (const float*)d_in[0];
    const float* h    = (const float*)d_in[1];
    const float* We   = (const float*)d_in[2];
    const float* be   = (const float*)d_in[3];
    const float* W1   = (const float*)d_in[4];
    const float* b1   = (const float*)d_in[5];
    const float* W2   = (const float*)d_in[6];
    const float* b2   = (const float*)d_in[7];
    const float* W3   = (const float*)d_in[8];
    const float* b3   = (const float*)d_in[9];
    float* out = (float*)d_out;

    prep_weights<<<512, 256>>>(W1, W2);

    cudaFuncSetAttribute(fused_hmma_kernel,
                         cudaFuncAttributeMaxDynamicSharedMemorySize, SM_TOTAL);
    fused_hmma_kernel<<<NCTA, NTHREADS, SM_TOTAL>>>(last, h, We, be, b1, b2, W3, b3, out);
}